// round 14
// baseline (speedup 1.0000x reference)
#include <cuda_runtime.h>
#include <cuda_fp16.h>
#include <math.h>
#include <limits.h>

#define VV 50257
#define EE 1024
#define HH 512
#define DD 1024
#define SS 64
#define KKB 4
#define MAXLEN 20
#define TOKL (MAXLEN + 1)
#define BOSTOK 1
#define EOSTOK 2
#define NSB 64
#define VCH 786          /* 64*786 >= 50257 */
#define RG8 6283         /* ceil(50257/8) 8-row groups */
#define NWARPS 2048      /* 256 blocks x 8 warps */

// ----------------- static device scratch -----------------
static __device__ __align__(16) float  g_X[SS * EE];
static __device__ __align__(16) float  g_Zf[SS * 4 * HH];
static __device__ __align__(16) float  g_Zb[4 * HH];
static __device__ __align__(16) float  g_eh[2][HH];
static __device__ __align__(16) float  g_ec[HH];
static __device__ __align__(16) float  g_sent[DD];
static __device__ float4 g_dh[2][DD];
static __device__ float4 g_dc[2][DD];
static __device__ float4 g_htmp[DD];
static __device__ float4 g_ctmp[DD];
static __device__ float4 g_outs[DD];
static __device__ float4 g_logits4[VV];
static __device__ float4 g_bmaxW[NWARPS];
static __device__ float4 g_bsum4[NSB];
static __device__ float  g_tval[NSB * 4];
static __device__ int    g_tidx[NSB * 4];
static __device__ float  g_probs[KKB];
static __device__ int    g_last[KKB];
static __device__ int    g_fin[KKB];
static __device__ int    g_tok[2][KKB * TOKL];

static __device__ __align__(16) __half g_Wout_h[(size_t)VV * DD];
static __device__ __align__(16) __half g_Wih_h[4 * DD * EE];
static __device__ __align__(16) __half g_Whh_h[4 * DD * DD];
static __device__ __align__(16) __half g_Wcat_h[DD * 2 * DD];
static __device__ __align__(16) __half g_Whhf_h[4 * HH * HH];

// ----------------- grid barriers (two independent counter pairs) -----------
static __device__ unsigned g_barcnt = 0, g_bargen = 0;     // full-grid / enc
static __device__ unsigned g_barcnt2 = 0, g_bargen2 = 0;   // 64-block subset
__device__ __forceinline__ void gbar(unsigned nblk, unsigned* cnt, unsigned* gen) {
    __syncthreads();
    if (threadIdx.x == 0) {
        __threadfence();
        unsigned g0 = atomicAdd(gen, 0u);
        if (atomicAdd(cnt, 1u) == nblk - 1) {
            atomicExch(cnt, 0u);
            __threadfence();
            atomicAdd(gen, 1u);
        } else {
            while (atomicAdd(gen, 0u) == g0) { __nanosleep(32); }
        }
        __threadfence();
    }
    __syncthreads();
}
__device__ __forceinline__ void bar256() { gbar(256, &g_barcnt, &g_bargen); }
__device__ __forceinline__ void bar64()  { gbar(64, &g_barcnt2, &g_bargen2); }

// ----------------- controlled-precision ops (LOAD-BEARING) ------------------
// FTZ product semantics verified round 5 (rel_err == 0). DO NOT CHANGE.
__device__ __forceinline__ float pmul_ftz(float a, float b) {
    float r;
    asm("mul.rn.ftz.f32 %0, %1, %2;" : "=f"(r) : "f"(a), "f"(b));
    return r;
}
__device__ __forceinline__ float fdiv_rn(float a, float b) {
    float r;
    asm("div.rn.f32 %0, %1, %2;" : "=f"(r) : "f"(a), "f"(b));
    return r;
}

// ----------------- helpers -----------------
__device__ __forceinline__ float sigm(float x) { return 1.0f / (1.0f + expf(-x)); }
__device__ __forceinline__ float wredsum(float v) {
#pragma unroll
    for (int o = 16; o; o >>= 1) v += __shfl_xor_sync(0xffffffffu, v, o);
    return v;
}
__device__ __forceinline__ float4 max4(float4 a, float4 b) {
    return make_float4(fmaxf(a.x, b.x), fmaxf(a.y, b.y), fmaxf(a.z, b.z), fmaxf(a.w, b.w));
}
__device__ __forceinline__ float4 add4(float4 a, float4 b) {
    return make_float4(a.x + b.x, a.y + b.y, a.z + b.z, a.w + b.w);
}
__device__ __forceinline__ void fma4(float4& a, float w, float4 x) {
    a.x = fmaf(w, x.x, a.x); a.y = fmaf(w, x.y, a.y);
    a.z = fmaf(w, x.z, a.z); a.w = fmaf(w, x.w, a.w);
}
__device__ __forceinline__ void redsum4(float4& a) {
    a.x = wredsum(a.x); a.y = wredsum(a.y); a.z = wredsum(a.z); a.w = wredsum(a.w);
}
__device__ __forceinline__ void fma8(float4& acc, uint4 wv, const float4* o) {
    __half2 h;
    h = *(__half2*)&wv.x; fma4(acc, __low2float(h), o[0]); fma4(acc, __high2float(h), o[1]);
    h = *(__half2*)&wv.y; fma4(acc, __low2float(h), o[2]); fma4(acc, __high2float(h), o[3]);
    h = *(__half2*)&wv.z; fma4(acc, __low2float(h), o[4]); fma4(acc, __high2float(h), o[5]);
    h = *(__half2*)&wv.w; fma4(acc, __low2float(h), o[6]); fma4(acc, __high2float(h), o[7]);
}
__device__ __forceinline__ void fma8s(float& acc, uint4 wv, const float* h) {
    __half2 x;
    x = *(__half2*)&wv.x; acc = fmaf(__low2float(x), h[0], acc); acc = fmaf(__high2float(x), h[1], acc);
    x = *(__half2*)&wv.y; acc = fmaf(__low2float(x), h[2], acc); acc = fmaf(__high2float(x), h[3], acc);
    x = *(__half2*)&wv.z; acc = fmaf(__low2float(x), h[4], acc); acc = fmaf(__high2float(x), h[5], acc);
    x = *(__half2*)&wv.w; acc = fmaf(__low2float(x), h[6], acc); acc = fmaf(__high2float(x), h[7], acc);
}
__device__ __forceinline__ bool cgt(float v1, int i1, float v2, int i2) {
    return (v1 > v2) || (v1 == v2 && i1 < i2);
}
__device__ __forceinline__ void ins4(float* lv, int* li, float v, int idx) {
    if (!cgt(v, idx, lv[3], li[3])) return;
    lv[3] = v; li[3] = idx;
#pragma unroll
    for (int j = 3; j > 0; j--) {
        if (cgt(lv[j], li[j], lv[j - 1], li[j - 1])) {
            float tv = lv[j]; lv[j] = lv[j - 1]; lv[j - 1] = tv;
            int ti = li[j]; li[j] = li[j - 1]; li[j - 1] = ti;
        } else break;
    }
}
__device__ __forceinline__ uint4 cvt8h(float4 v0, float4 v1) {
    __half2 a = __floats2half2_rn(v0.x, v0.y);
    __half2 b = __floats2half2_rn(v0.z, v0.w);
    __half2 c = __floats2half2_rn(v1.x, v1.y);
    __half2 d = __floats2half2_rn(v1.z, v1.w);
    return make_uint4(*(unsigned*)&a, *(unsigned*)&b, *(unsigned*)&c, *(unsigned*)&d);
}

// ----------------- fp32 -> fp16 conversions (small weights) -----------------
#define CVT_BODY(DST) \
    unsigned s = gridDim.x * blockDim.x; \
    unsigned i0 = blockIdx.x * blockDim.x + threadIdx.x; \
    unsigned i1 = i0 + s, i2 = i0 + 2u * s, i3 = i0 + 3u * s; \
    float4 a0, b0, a1, b1, a2, b2, a3, b3; \
    if (i0 < (unsigned)n8) { a0 = __ldcs(&src[2 * (size_t)i0]); b0 = __ldcs(&src[2 * (size_t)i0 + 1]); } \
    if (i1 < (unsigned)n8) { a1 = __ldcs(&src[2 * (size_t)i1]); b1 = __ldcs(&src[2 * (size_t)i1 + 1]); } \
    if (i2 < (unsigned)n8) { a2 = __ldcs(&src[2 * (size_t)i2]); b2 = __ldcs(&src[2 * (size_t)i2 + 1]); } \
    if (i3 < (unsigned)n8) { a3 = __ldcs(&src[2 * (size_t)i3]); b3 = __ldcs(&src[2 * (size_t)i3 + 1]); } \
    if (i0 < (unsigned)n8) ((uint4*)DST)[i0] = cvt8h(a0, b0); \
    if (i1 < (unsigned)n8) ((uint4*)DST)[i1] = cvt8h(a1, b1); \
    if (i2 < (unsigned)n8) ((uint4*)DST)[i2] = cvt8h(a2, b2); \
    if (i3 < (unsigned)n8) ((uint4*)DST)[i3] = cvt8h(a3, b3);
__global__ void k_cvt_ih (const float4* __restrict__ src, int n8) { CVT_BODY(g_Wih_h) }
__global__ void k_cvt_hh (const float4* __restrict__ src, int n8) { CVT_BODY(g_Whh_h) }
__global__ void k_cvt_cat(const float4* __restrict__ src, int n8) { CVT_BODY(g_Wcat_h) }
__global__ void k_cvt_enc(const float4* __restrict__ src, int n8) { CVT_BODY(g_Whhf_h) }

// ----------------- setup kernels -----------------
__global__ void k_init0() {
    int u = threadIdx.x;
    if (u < HH) { g_eh[0][u] = 0.0f; g_eh[1][u] = 0.0f; g_ec[u] = 0.0f; }
}
__global__ void k_gather(const int* __restrict__ sent, const float* __restrict__ emb) {
    int t = blockIdx.x;
    const float4* src = (const float4*)(emb + (size_t)sent[t] * EE);
    float4* dst = (float4*)(g_X + t * EE);
    for (int e = threadIdx.x; e < EE / 4; e += blockDim.x) dst[e] = src[e];
}
__global__ void k_zxf(const float* __restrict__ W, const float* __restrict__ b) {
    __shared__ __align__(16) float xs[8 * EE];
    int w = threadIdx.x >> 5, lane = threadIdx.x & 31;
    int j = blockIdx.x * 8 + w;
    const float4* wr4 = (const float4*)(W + (size_t)j * EE);
    float bj = b[j];
    for (int tc = 0; tc < 8; tc++) {
        __syncthreads();
        {
            const float4* src = (const float4*)(g_X + tc * 8 * EE);
            float4* dst = (float4*)xs;
            for (int i = threadIdx.x; i < 8 * EE / 4; i += blockDim.x) dst[i] = src[i];
        }
        __syncthreads();
        for (int tt = 0; tt < 8; tt++) {
            float acc = 0.0f;
            const float4* x4 = (const float4*)(xs + tt * EE);
#pragma unroll
            for (int i = 0; i < 8; i++) {
                int cq = lane + 32 * i;
                float4 wv = wr4[cq], xv = x4[cq];
                acc = fmaf(wv.x, xv.x, acc); acc = fmaf(wv.y, xv.y, acc);
                acc = fmaf(wv.z, xv.z, acc); acc = fmaf(wv.w, xv.w, acc);
            }
            acc = wredsum(acc);
            if (lane == 0) g_Zf[(tc * 8 + tt) * (4 * HH) + j] = acc + bj;
        }
    }
}
__global__ void k_zb(const float* __restrict__ W, const float* __restrict__ b) {
    __shared__ __align__(16) float xs[EE];
    {
        const float4* src = (const float4*)(g_X + (SS - 1) * EE);
        float4* dst = (float4*)xs;
        for (int i = threadIdx.x; i < EE / 4; i += blockDim.x) dst[i] = src[i];
    }
    __syncthreads();
    int j = blockIdx.x * 8 + (threadIdx.x >> 5), lane = threadIdx.x & 31;
    const float4* wr4 = (const float4*)(W + (size_t)j * EE);
    const float4* x4 = (const float4*)xs;
    float acc = 0.0f;
#pragma unroll
    for (int i = 0; i < 8; i++) {
        int cq = lane + 32 * i;
        float4 wv = wr4[cq], xv = x4[cq];
        acc = fmaf(wv.x, xv.x, acc); acc = fmaf(wv.y, xv.y, acc);
        acc = fmaf(wv.z, xv.z, acc); acc = fmaf(wv.w, xv.w, acc);
    }
    acc = wredsum(acc);
    if (lane == 0) g_Zb[j] = acc + b[j];
}
__global__ void k_enc_all() {
    __shared__ float hT[8 * 64];
    int tid = threadIdx.x;
    int u = blockIdx.x * 16 + (tid >> 5), lane = tid & 31;
    const uint4* WE = (const uint4*)g_Whhf_h;
    for (int t = 0; t < SS; t++) {
        int p = t & 1;
        if (tid < HH)
            hT[(tid & 7) * 64 + (tid >> 3)] = __ldcg(&g_eh[p][tid]);
        __syncthreads();
        float z[4] = {0.f, 0.f, 0.f, 0.f};
#pragma unroll
        for (int i = 0; i < 2; i++) {
            int cq = lane + 32 * i;
            float h[8];
#pragma unroll
            for (int j = 0; j < 8; j++) h[j] = hT[j * 64 + cq];
#pragma unroll
            for (int g = 0; g < 4; g++) {
                uint4 wv = WE[(size_t)(g * HH + u) * 64 + cq];
                fma8s(z[g], wv, h);
            }
        }
#pragma unroll
        for (int g = 0; g < 4; g++) z[g] = wredsum(z[g]);
        if (lane == 0) {
            const float* zx = g_Zf + t * (4 * HH);
            float zi = zx[u] + z[0], zf = zx[HH + u] + z[1];
            float zg = zx[2 * HH + u] + z[2], zo = zx[3 * HH + u] + z[3];
            float c = sigm(zf) * g_ec[u] + sigm(zi) * tanhf(zg);
            g_ec[u] = c;
            g_eh[p ^ 1][u] = sigm(zo) * tanhf(c);
        }
        gbar(32, &g_barcnt, &g_bargen);
    }
}
__global__ void k_init2() {
    int u = threadIdx.x;
    if (u < HH) {
        float zi = g_Zb[u], zg = g_Zb[2 * HH + u], zo = g_Zb[3 * HH + u];
        float c = sigm(zi) * tanhf(zg);
        float hb = sigm(zo) * tanhf(c);
        g_sent[u] = g_eh[0][u];
        g_sent[HH + u] = hb;
    }
    __syncthreads();
    for (int d = u; d < DD; d += blockDim.x) {
        float s = g_sent[d];
        g_dh[0][d] = make_float4(s, s, s, s);
        g_dc[0][d] = make_float4(0.f, 0.f, 0.f, 0.f);
    }
    if (u < KKB) {
        g_probs[u] = (u == 0) ? 1.0f : 0.0f;
        g_last[u] = BOSTOK;
        g_fin[u] = 0;
        for (int i = 0; i < TOKL; i++) g_tok[0][u * TOKL + i] = BOSTOK;
    }
}

// ================= persistent decode kernel: all 20 steps =================
__global__ void __launch_bounds__(256, 2)
k_decode(const float* __restrict__ demb, const float* __restrict__ db,
         const float* __restrict__ cat_b, const float* __restrict__ Wout32,
         const float* __restrict__ out_b, float* out, int out_size) {
    __shared__ __align__(16) float4 smA[2048];   // 32 KB (dec eT/hT, cat fT, logits oT)
    __shared__ float4 red[256];
    __shared__ float cvv[256][4];
    __shared__ int   cii[256][4];
    __shared__ int parent[4], tokn[4], nfin[4];
    __shared__ float topv[4];

    int tid = threadIdx.x, blk = blockIdx.x;
    int w = tid >> 5, lane = tid & 31;
    const uint4* W1 = (const uint4*)g_Wih_h;
    const uint4* W2 = (const uint4*)g_Whh_h;
    const uint4* WC = (const uint4*)g_Wcat_h;
    const uint4* W16 = (const uint4*)g_Wout_h;
    const float4* W32 = (const float4*)Wout32;

#pragma unroll 1
    for (int t = 0; t < MAXLEN; t++) {
        int p = t & 1;

        // ---- phase A: dec LSTM gates (blocks 0..127) ----
        if (blk < 128) {
            int l0 = __ldcg(&g_last[0]), l1 = __ldcg(&g_last[1]);
            int l2 = __ldcg(&g_last[2]), l3 = __ldcg(&g_last[3]);
            float4* eT = smA;            // [8][128]
            float4* hT = smA + 1024;
            for (int a = tid; a < DD; a += 256) {
                int j = a & 7, cq = a >> 3;
                eT[j * 128 + cq] = make_float4(demb[(size_t)l0 * EE + a], demb[(size_t)l1 * EE + a],
                                               demb[(size_t)l2 * EE + a], demb[(size_t)l3 * EE + a]);
                hT[j * 128 + cq] = __ldcg(&g_dh[p][a]);
            }
            __syncthreads();
            int u = blk * 8 + w;
            float4 acc[4];
#pragma unroll
            for (int g = 0; g < 4; g++) acc[g] = make_float4(0.f, 0.f, 0.f, 0.f);
#pragma unroll
            for (int i = 0; i < 4; i++) {
                int cq = lane + 32 * i;
                float4 e[8];
#pragma unroll
                for (int j = 0; j < 8; j++) e[j] = eT[j * 128 + cq];
#pragma unroll
                for (int g = 0; g < 4; g++)
                    fma8(acc[g], W1[(size_t)(g * DD + u) * 128 + cq], e);
            }
#pragma unroll
            for (int i = 0; i < 4; i++) {
                int cq = lane + 32 * i;
                float4 h[8];
#pragma unroll
                for (int j = 0; j < 8; j++) h[j] = hT[j * 128 + cq];
#pragma unroll
                for (int g = 0; g < 4; g++)
                    fma8(acc[g], W2[(size_t)(g * DD + u) * 128 + cq], h);
            }
#pragma unroll
            for (int g = 0; g < 4; g++) redsum4(acc[g]);
            if (lane == 0) {
                float bi = db[u], bf = db[DD + u], bg = db[2 * DD + u], bo = db[3 * DD + u];
                float4 c4 = __ldcg(&g_dc[p][u]);
                float4 cn, hn;
                cn.x = sigm(acc[1].x + bf) * c4.x + sigm(acc[0].x + bi) * tanhf(acc[2].x + bg);
                cn.y = sigm(acc[1].y + bf) * c4.y + sigm(acc[0].y + bi) * tanhf(acc[2].y + bg);
                cn.z = sigm(acc[1].z + bf) * c4.z + sigm(acc[0].z + bi) * tanhf(acc[2].z + bg);
                cn.w = sigm(acc[1].w + bf) * c4.w + sigm(acc[0].w + bi) * tanhf(acc[2].w + bg);
                hn.x = sigm(acc[3].x + bo) * tanhf(cn.x);
                hn.y = sigm(acc[3].y + bo) * tanhf(cn.y);
                hn.z = sigm(acc[3].z + bo) * tanhf(cn.z);
                hn.w = sigm(acc[3].w + bo) * tanhf(cn.w);
                g_htmp[u] = hn;
                g_ctmp[u] = cn;
            }
        }
        bar256();

        // ---- phase B: cat + tanh (blocks 0..127) ----
        if (blk < 128) {
            int l0 = __ldcg(&g_last[0]), l1 = __ldcg(&g_last[1]);
            int l2 = __ldcg(&g_last[2]), l3 = __ldcg(&g_last[3]);
            for (int a = tid; a < 2 * DD; a += 256) {
                int j = a & 7, cq = a >> 3;
                float4 v;
                if (a < DD) v = __ldcg(&g_htmp[a]);
                else {
                    int e = a - DD;
                    v = make_float4(demb[(size_t)l0 * EE + e], demb[(size_t)l1 * EE + e],
                                    demb[(size_t)l2 * EE + e], demb[(size_t)l3 * EE + e]);
                }
                smA[j * 256 + cq] = v;   // fT[8][256]
            }
            __syncthreads();
            int u = blk * 8 + w;
            float4 a4 = make_float4(0.f, 0.f, 0.f, 0.f);
#pragma unroll
            for (int i = 0; i < 8; i++) {
                int cq = lane + 32 * i;
                float4 f[8];
#pragma unroll
                for (int j = 0; j < 8; j++) f[j] = smA[j * 256 + cq];
                fma8(a4, WC[(size_t)u * 256 + cq], f);
            }
            redsum4(a4);
            if (lane == 0) {
                float bd = cat_b[u];
                g_outs[u] = make_float4(tanhf(a4.x + bd), tanhf(a4.y + bd),
                                        tanhf(a4.z + bd), tanhf(a4.w + bd));
            }
        }
        bar256();

        // ---- phase C: logits (all blocks, warp-granular 8-row groups) ----
        {
            float4* oT = smA;   // [8][128]
            for (int a = tid; a < DD; a += 256) {
                int j = a & 7, cq = a >> 3;
                oT[j * 128 + cq] = __ldcg(&g_outs[a]);
            }
            __syncthreads();
            int gw = blk * 8 + w;
            float4 m = make_float4(-INFINITY, -INFINITY, -INFINITY, -INFINITY);
            for (int k8 = gw; k8 < RG8; k8 += NWARPS) {
                int vbase = k8 * 8;
                float4 acc[8];
#pragma unroll
                for (int r = 0; r < 8; r++) acc[r] = make_float4(0.f, 0.f, 0.f, 0.f);
#pragma unroll
                for (int i = 0; i < 4; i++) {
                    int cq = lane + 32 * i;
                    float4 o[8];
#pragma unroll
                    for (int j = 0; j < 8; j++) o[j] = oT[j * 128 + cq];
#pragma unroll
                    for (int r = 0; r < 8; r++) {
                        int v = vbase + r; if (v >= VV) v = VV - 1;
                        uint4 wv;
                        if (t == 0) {
                            float4 w0 = __ldcs(&W32[(size_t)v * 256 + 2 * cq]);
                            float4 w1 = __ldcs(&W32[(size_t)v * 256 + 2 * cq + 1]);
                            wv = cvt8h(w0, w1);
                            __stcs((uint4*)&W16[(size_t)v * 128 + cq], wv);
                        } else {
                            wv = __ldcs(&W16[(size_t)v * 128 + cq]);
                        }
                        fma8(acc[r], wv, o);
                    }
                }
#pragma unroll
                for (int r = 0; r < 8; r++) {
                    redsum4(acc[r]);
                    int v = vbase + r;
                    if (lane == 0 && v < VV) {
                        float bb = out_b[v];
                        acc[r].x += bb; acc[r].y += bb; acc[r].z += bb; acc[r].w += bb;
                        g_logits4[v] = acc[r];
                        m = max4(m, acc[r]);
                    }
                }
            }
            // lane 0 holds the exact per-warp max (all updates lane-0 guarded)
            if (lane == 0) g_bmaxW[gw] = m;
        }
        bar256();

        // ---- phase D: global max + per-chunk exp-sum (blocks 0..63) ----
        if (blk < 64) {
            float4 m = make_float4(-INFINITY, -INFINITY, -INFINITY, -INFINITY);
            for (int i = tid; i < NWARPS; i += 256) m = max4(m, __ldcg(&g_bmaxW[i]));
            red[tid] = m; __syncthreads();
            for (int s = 128; s; s >>= 1) {
                if (tid < s) red[tid] = max4(red[tid], red[tid + s]);
                __syncthreads();
            }
            float4 gm = red[0]; __syncthreads();

            float4 sum = make_float4(0.f, 0.f, 0.f, 0.f);
            int base = blk * VCH;
            for (int i = tid; i < VCH; i += 256) {
                int v = base + i;
                if (v >= VV) break;
                float4 l = __ldcg(&g_logits4[v]);
                sum.x += expf(l.x - gm.x); sum.y += expf(l.y - gm.y);
                sum.z += expf(l.z - gm.z); sum.w += expf(l.w - gm.w);
            }
            red[tid] = sum; __syncthreads();
            for (int s = 128; s; s >>= 1) {
                if (tid < s) red[tid] = add4(red[tid], red[tid + s]);
                __syncthreads();
            }
            if (tid == 0) g_bsum4[blk] = red[0];
            bar64();

            // ---- phase E: global sum + per-chunk top-4 ----
            float4 sm = (tid < NSB) ? __ldcg(&g_bsum4[tid]) : make_float4(0.f, 0.f, 0.f, 0.f);
            red[tid] = sm; __syncthreads();
            for (int s = 128; s; s >>= 1) {
                if (tid < s) red[tid] = add4(red[tid], red[tid + s]);
                __syncthreads();
            }
            float4 tot = red[0]; __syncthreads();

            float pr[4] = {__ldcg(&g_probs[0]), __ldcg(&g_probs[1]), __ldcg(&g_probs[2]), __ldcg(&g_probs[3])};
            int   fn[4] = {__ldcg(&g_fin[0]), __ldcg(&g_fin[1]), __ldcg(&g_fin[2]), __ldcg(&g_fin[3])};
            float gmk[4] = {gm.x, gm.y, gm.z, gm.w};
            float tk[4]  = {tot.x, tot.y, tot.z, tot.w};

            float lv[4] = {-INFINITY, -INFINITY, -INFINITY, -INFINITY};
            int   li[4] = {INT_MAX, INT_MAX, INT_MAX, INT_MAX};
            int base2 = blk * VCH;
            for (int i = tid; i < VCH; i += 256) {
                int v = base2 + i;
                if (v >= VV) break;
                float4 l = __ldcg(&g_logits4[v]);
                float lk[4] = {l.x, l.y, l.z, l.w};
#pragma unroll
                for (int k = 0; k < 4; k++) {
                    float pp = fn[k] ? (v == EOSTOK ? 1.0f : 0.0f)
                                     : fdiv_rn(expf(lk[k] - gmk[k]), tk[k]);
                    ins4(lv, li, pmul_ftz(pr[k], pp), k * VV + v);  // FTZ: DO NOT CHANGE
                }
            }
#pragma unroll
            for (int k = 0; k < 4; k++) { cvv[tid][k] = lv[k]; cii[tid][k] = li[k]; }
            __syncthreads();
            for (int s = 128; s; s >>= 1) {
                if (tid < s) {
                    float av[4]; int ai[4];
#pragma unroll
                    for (int k = 0; k < 4; k++) { av[k] = cvv[tid][k]; ai[k] = cii[tid][k]; }
#pragma unroll
                    for (int k = 0; k < 4; k++) ins4(av, ai, cvv[tid + s][k], cii[tid + s][k]);
#pragma unroll
                    for (int k = 0; k < 4; k++) { cvv[tid][k] = av[k]; cii[tid][k] = ai[k]; }
                }
                __syncthreads();
            }
            if (tid == 0) {
#pragma unroll
                for (int k = 0; k < 4; k++) { g_tval[blk * 4 + k] = cvv[0][k]; g_tidx[blk * 4 + k] = cii[0][k]; }
            }
            bar64();

            // ---- phase F: final merge + beam-state update (block 0) ----
            if (blk == 0) {
                if (tid < NSB) {
#pragma unroll
                    for (int k = 0; k < 4; k++) {
                        cvv[tid][k] = __ldcg(&g_tval[tid * 4 + k]);
                        cii[tid][k] = __ldcg(&g_tidx[tid * 4 + k]);
                    }
                }
                __syncthreads();
                for (int s = 32; s; s >>= 1) {
                    if (tid < s) {
                        float av[4]; int ai[4];
#pragma unroll
                        for (int k = 0; k < 4; k++) { av[k] = cvv[tid][k]; ai[k] = cii[tid][k]; }
#pragma unroll
                        for (int k = 0; k < 4; k++) ins4(av, ai, cvv[tid + s][k], cii[tid + s][k]);
#pragma unroll
                        for (int k = 0; k < 4; k++) { cvv[tid][k] = av[k]; cii[tid][k] = ai[k]; }
                    }
                    __syncthreads();
                }
                if (tid == 0) {
                    int ofin[4] = {__ldcg(&g_fin[0]), __ldcg(&g_fin[1]), __ldcg(&g_fin[2]), __ldcg(&g_fin[3])};
#pragma unroll
                    for (int k = 0; k < 4; k++) {
                        topv[k] = cvv[0][k];
                        int idx = cii[0][k];
                        parent[k] = idx / VV;
                        tokn[k] = idx % VV;
                        nfin[k] = ofin[idx / VV] | ((idx % VV) == EOSTOK);
                    }
                }
                __syncthreads();
                if (tid < KKB * TOKL) {
                    int k = tid / TOKL, i = tid % TOKL;
                    int val = (i == t + 1) ? tokn[k] : g_tok[p][parent[k] * TOKL + i];
                    g_tok[p ^ 1][k * TOKL + i] = val;
                }
                for (int d = tid; d < DD; d += 256) {
                    float4 h = __ldcg(&g_htmp[d]), c = __ldcg(&g_ctmp[d]);
                    float hh[4] = {h.x, h.y, h.z, h.w};
                    float cc[4] = {c.x, c.y, c.z, c.w};
                    g_dh[p ^ 1][d] = make_float4(hh[parent[0]], hh[parent[1]], hh[parent[2]], hh[parent[3]]);
                    g_dc[p ^ 1][d] = make_float4(cc[parent[0]], cc[parent[1]], cc[parent[2]], cc[parent[3]]);
                }
                if (tid < KKB) {
                    g_probs[tid] = topv[tid];
                    g_last[tid] = tokn[tid];
                    g_fin[tid] = nfin[tid];
                }
                __syncthreads();
                if (t == MAXLEN - 1 && tid == 0) {
                    int best = 0; float bv = topv[0];
                    for (int k = 1; k < 4; k++) if (topv[k] > bv) { bv = topv[k]; best = k; }
                    if (out_size >= TOKL + KKB) {
                        for (int i = 0; i < TOKL; i++) out[i] = (float)g_tok[p ^ 1][best * TOKL + i];
                        for (int k = 0; k < KKB; k++) out[TOKL + k] = topv[k];
                    } else if (out_size == TOKL) {
                        int* io = (int*)out;
                        for (int i = 0; i < TOKL; i++) io[i] = g_tok[p ^ 1][best * TOKL + i];
                    } else if (out_size == KKB) {
                        for (int k = 0; k < KKB; k++) out[k] = topv[k];
                    } else {
                        int n = out_size < TOKL ? out_size : TOKL;
                        for (int i = 0; i < n; i++) out[i] = (float)g_tok[p ^ 1][best * TOKL + i];
                    }
                }
            }
        }
        bar256();   // end of step
    }
}

// ----------------- launch -----------------
extern "C" void kernel_launch(void* const* d_in, const int* in_sizes, int n_in,
                              void* d_out, int out_size) {
    const int*   sent      = (const int*)d_in[0];
    const float* enc_emb   = (const float*)d_in[1];
    const float* enc_Wih_f = (const float*)d_in[2];
    const float* enc_Whh_f = (const float*)d_in[3];
    const float* enc_b_f   = (const float*)d_in[4];
    const float* enc_Wih_b = (const float*)d_in[5];
    const float* enc_b_b   = (const float*)d_in[7];
    const float* dec_emb   = (const float*)d_in[8];
    const float* dec_Wih   = (const float*)d_in[9];
    const float* dec_Whh   = (const float*)d_in[10];
    const float* dec_b     = (const float*)d_in[11];
    const float* cat_W     = (const float*)d_in[12];
    const float* cat_b     = (const float*)d_in[13];
    const float* out_W     = (const float*)d_in[14];
    const float* out_b     = (const float*)d_in[15];
    (void)in_sizes; (void)n_in;

    k_init0<<<1, 512>>>();
    k_gather<<<SS, 256>>>(sent, enc_emb);
    {
        int n8, nb;
        n8 = (4 * HH * HH) / 8;  nb = (n8 + 2047) / 2048;  k_cvt_enc<<<nb, 512>>>((const float4*)enc_Whh_f, n8);
        n8 = (4 * DD * EE) / 8;  nb = (n8 + 2047) / 2048;  k_cvt_ih <<<nb, 512>>>((const float4*)dec_Wih, n8);
        n8 = (4 * DD * DD) / 8;  nb = (n8 + 2047) / 2048;  k_cvt_hh <<<nb, 512>>>((const float4*)dec_Whh, n8);
        n8 = (DD * 2 * DD) / 8;  nb = (n8 + 2047) / 2048;  k_cvt_cat<<<nb, 512>>>((const float4*)cat_W, n8);
    }
    k_zxf<<<256, 256>>>(enc_Wih_f, enc_b_f);
    k_zb<<<256, 256>>>(enc_Wih_b, enc_b_b);
    k_enc_all<<<32, 512>>>();
    k_init2<<<1, 512>>>();
    k_decode<<<256, 256>>>(dec_emb, dec_b, cat_b, out_W, out_b, (float*)d_out, out_size);
}

// round 15
// speedup vs baseline: 1.2239x; 1.2239x over previous
#include <cuda_runtime.h>
#include <cuda_fp16.h>
#include <math.h>
#include <limits.h>

#define VV 50257
#define EE 1024
#define HH 512
#define DD 1024
#define SS 64
#define KKB 4
#define MAXLEN 20
#define TOKL (MAXLEN + 1)
#define BOSTOK 1
#define EOSTOK 2
#define NLB 1571         /* logits blocks: 1571*32 >= 50257 (4 rows/warp, 8 warps) */
#define NSB 64           /* select blocks */
#define VCH 786          /* 64*786 >= 50257 */

// ----------------- static device scratch (no allocation) -----------------
static __device__ __align__(16) float  g_X[SS * EE];
static __device__ __align__(16) float  g_Zf[SS * 4 * HH];
static __device__ __align__(16) float  g_Zb[4 * HH];
static __device__ __align__(16) float  g_eh[2][HH];
static __device__ __align__(16) float  g_ec[HH];
static __device__ __align__(16) float  g_sent[DD];
static __device__ float4 g_dh[2][DD];
static __device__ float4 g_dc[2][DD];
static __device__ float4 g_htmp[DD];
static __device__ float4 g_ctmp[DD];
static __device__ float4 g_outs[DD];
static __device__ float4 g_logits4[VV];
static __device__ float4 g_bmax4[NLB];
static __device__ float4 g_bsum4[NSB];
static __device__ float  g_tval[NSB * 4];
static __device__ int    g_tidx[NSB * 4];
static __device__ float  g_probs[KKB];
static __device__ int    g_last[KKB];
static __device__ int    g_fin[KKB];
static __device__ int    g_tok[2][KKB * TOKL];

// fp16 weight copies (converted once per kernel_launch call)
static __device__ __align__(16) __half g_Wout_h[(size_t)VV * DD];   // 103 MB
static __device__ __align__(16) __half g_Wih_h[4 * DD * EE];
static __device__ __align__(16) __half g_Whh_h[4 * DD * DD];
static __device__ __align__(16) __half g_Wcat_h[DD * 2 * DD];
static __device__ __align__(16) __half g_Whhf_h[4 * HH * HH];

// ----------------- software grid barrier (sense-reversing, self-resetting) ---
static __device__ unsigned g_barcnt = 0;
static __device__ unsigned g_bargen = 0;
__device__ __forceinline__ void gridbar(unsigned nblk) {
    __syncthreads();
    if (threadIdx.x == 0) {
        __threadfence();
        unsigned gen = atomicAdd(&g_bargen, 0u);      // read epoch BEFORE arriving
        if (atomicAdd(&g_barcnt, 1u) == nblk - 1) {
            atomicExch(&g_barcnt, 0u);
            __threadfence();
            atomicAdd(&g_bargen, 1u);
        } else {
            while (atomicAdd(&g_bargen, 0u) == gen) { __nanosleep(32); }
        }
        __threadfence();
    }
    __syncthreads();
}

// ----------------- controlled-precision scalar ops (LOAD-BEARING) -----------
// FTZ multiply for the beam-prob candidate product: the reference runtime
// flushes subnormal results to zero (verified round 5: rel_err == 0).
__device__ __forceinline__ float pmul_ftz(float a, float b) {
    float r;
    asm("mul.rn.ftz.f32 %0, %1, %2;" : "=f"(r) : "f"(a), "f"(b));
    return r;
}
__device__ __forceinline__ float fdiv_rn(float a, float b) {
    float r;
    asm("div.rn.f32 %0, %1, %2;" : "=f"(r) : "f"(a), "f"(b));
    return r;
}

// ----------------- helpers -----------------
__device__ __forceinline__ float sigm(float x) { return 1.0f / (1.0f + expf(-x)); }
__device__ __forceinline__ float wredsum(float v) {
#pragma unroll
    for (int o = 16; o; o >>= 1) v += __shfl_xor_sync(0xffffffffu, v, o);
    return v;
}
__device__ __forceinline__ float4 max4(float4 a, float4 b) {
    return make_float4(fmaxf(a.x, b.x), fmaxf(a.y, b.y), fmaxf(a.z, b.z), fmaxf(a.w, b.w));
}
__device__ __forceinline__ float4 add4(float4 a, float4 b) {
    return make_float4(a.x + b.x, a.y + b.y, a.z + b.z, a.w + b.w);
}
__device__ __forceinline__ void fma4(float4& a, float w, float4 x) {
    a.x = fmaf(w, x.x, a.x); a.y = fmaf(w, x.y, a.y);
    a.z = fmaf(w, x.z, a.z); a.w = fmaf(w, x.w, a.w);
}
__device__ __forceinline__ void redsum4(float4& a) {
    a.x = wredsum(a.x); a.y = wredsum(a.y); a.z = wredsum(a.z); a.w = wredsum(a.w);
}
// 8 fp16 weights (one uint4) against 8 beam-float4 activations
__device__ __forceinline__ void fma8(float4& acc, uint4 wv, const float4* o) {
    __half2 h;
    h = *(__half2*)&wv.x; fma4(acc, __low2float(h), o[0]); fma4(acc, __high2float(h), o[1]);
    h = *(__half2*)&wv.y; fma4(acc, __low2float(h), o[2]); fma4(acc, __high2float(h), o[3]);
    h = *(__half2*)&wv.z; fma4(acc, __low2float(h), o[4]); fma4(acc, __high2float(h), o[5]);
    h = *(__half2*)&wv.w; fma4(acc, __low2float(h), o[6]); fma4(acc, __high2float(h), o[7]);
}
__device__ __forceinline__ void fma8s(float& acc, uint4 wv, const float* h) {
    __half2 x;
    x = *(__half2*)&wv.x; acc = fmaf(__low2float(x), h[0], acc); acc = fmaf(__high2float(x), h[1], acc);
    x = *(__half2*)&wv.y; acc = fmaf(__low2float(x), h[2], acc); acc = fmaf(__high2float(x), h[3], acc);
    x = *(__half2*)&wv.z; acc = fmaf(__low2float(x), h[4], acc); acc = fmaf(__high2float(x), h[5], acc);
    x = *(__half2*)&wv.w; acc = fmaf(__low2float(x), h[6], acc); acc = fmaf(__high2float(x), h[7], acc);
}

// top-k comparator: larger value wins; tie -> smaller flat index (JAX top_k)
__device__ __forceinline__ bool cgt(float v1, int i1, float v2, int i2) {
    return (v1 > v2) || (v1 == v2 && i1 < i2);
}
__device__ __forceinline__ void ins4(float* lv, int* li, float v, int idx) {
    if (!cgt(v, idx, lv[3], li[3])) return;
    lv[3] = v; li[3] = idx;
#pragma unroll
    for (int j = 3; j > 0; j--) {
        if (cgt(lv[j], li[j], lv[j - 1], li[j - 1])) {
            float tv = lv[j]; lv[j] = lv[j - 1]; lv[j - 1] = tv;
            int ti = li[j]; li[j] = li[j - 1]; li[j - 1] = ti;
        } else break;
    }
}

// ----------------- fp32 -> fp16 conversion: 4 strided uint4 per thread --------
__device__ __forceinline__ uint4 cvt8h(float4 v0, float4 v1) {
    __half2 a = __floats2half2_rn(v0.x, v0.y);
    __half2 b = __floats2half2_rn(v0.z, v0.w);
    __half2 c = __floats2half2_rn(v1.x, v1.y);
    __half2 d = __floats2half2_rn(v1.z, v1.w);
    return make_uint4(*(unsigned*)&a, *(unsigned*)&b, *(unsigned*)&c, *(unsigned*)&d);
}
#define CVT_BODY(DST) \
    unsigned s = gridDim.x * blockDim.x; \
    unsigned i0 = blockIdx.x * blockDim.x + threadIdx.x; \
    unsigned i1 = i0 + s, i2 = i0 + 2u * s, i3 = i0 + 3u * s; \
    float4 a0, b0, a1, b1, a2, b2, a3, b3; \
    if (i0 < (unsigned)n8) { a0 = __ldcs(&src[2 * (size_t)i0]); b0 = __ldcs(&src[2 * (size_t)i0 + 1]); } \
    if (i1 < (unsigned)n8) { a1 = __ldcs(&src[2 * (size_t)i1]); b1 = __ldcs(&src[2 * (size_t)i1 + 1]); } \
    if (i2 < (unsigned)n8) { a2 = __ldcs(&src[2 * (size_t)i2]); b2 = __ldcs(&src[2 * (size_t)i2 + 1]); } \
    if (i3 < (unsigned)n8) { a3 = __ldcs(&src[2 * (size_t)i3]); b3 = __ldcs(&src[2 * (size_t)i3 + 1]); } \
    if (i0 < (unsigned)n8) ((uint4*)DST)[i0] = cvt8h(a0, b0); \
    if (i1 < (unsigned)n8) ((uint4*)DST)[i1] = cvt8h(a1, b1); \
    if (i2 < (unsigned)n8) ((uint4*)DST)[i2] = cvt8h(a2, b2); \
    if (i3 < (unsigned)n8) ((uint4*)DST)[i3] = cvt8h(a3, b3);
__global__ void k_cvt_out(const float4* __restrict__ src, int n8) { CVT_BODY(g_Wout_h) }
__global__ void k_cvt_ih (const float4* __restrict__ src, int n8) { CVT_BODY(g_Wih_h) }
__global__ void k_cvt_hh (const float4* __restrict__ src, int n8) { CVT_BODY(g_Whh_h) }
__global__ void k_cvt_cat(const float4* __restrict__ src, int n8) { CVT_BODY(g_Wcat_h) }
__global__ void k_cvt_enc(const float4* __restrict__ src, int n8) { CVT_BODY(g_Whhf_h) }

// ----------------- init: zero encoder state -----------------
__global__ void k_init0() {
    int u = threadIdx.x;
    if (u < HH) { g_eh[0][u] = 0.0f; g_eh[1][u] = 0.0f; g_ec[u] = 0.0f; }
}

// ----------------- gather embedded sentence -----------------
__global__ void k_gather(const int* __restrict__ sent, const float* __restrict__ emb) {
    int t = blockIdx.x;
    const float4* src = (const float4*)(emb + (size_t)sent[t] * EE);
    float4* dst = (float4*)(g_X + t * EE);
    for (int e = threadIdx.x; e < EE / 4; e += blockDim.x) dst[e] = src[e];
}

// ----------------- Zx_f = X @ Wih_f^T + b (fp32, one-time) -----------------
__global__ void k_zxf(const float* __restrict__ W, const float* __restrict__ b) {
    __shared__ __align__(16) float xs[8 * EE];
    int w = threadIdx.x >> 5, lane = threadIdx.x & 31;
    int j = blockIdx.x * 8 + w;
    const float4* wr4 = (const float4*)(W + (size_t)j * EE);
    float bj = b[j];
    for (int tc = 0; tc < 8; tc++) {
        __syncthreads();
        {
            const float4* src = (const float4*)(g_X + tc * 8 * EE);
            float4* dst = (float4*)xs;
            for (int i = threadIdx.x; i < 8 * EE / 4; i += blockDim.x) dst[i] = src[i];
        }
        __syncthreads();
        for (int tt = 0; tt < 8; tt++) {
            float acc = 0.0f;
            const float4* x4 = (const float4*)(xs + tt * EE);
#pragma unroll
            for (int i = 0; i < 8; i++) {
                int cq = lane + 32 * i;
                float4 wv = wr4[cq], xv = x4[cq];
                acc = fmaf(wv.x, xv.x, acc); acc = fmaf(wv.y, xv.y, acc);
                acc = fmaf(wv.z, xv.z, acc); acc = fmaf(wv.w, xv.w, acc);
            }
            acc = wredsum(acc);
            if (lane == 0) g_Zf[(tc * 8 + tt) * (4 * HH) + j] = acc + bj;
        }
    }
}

// ----------------- Zb = x_last @ Wih_b^T + b_b (fp32, one-time) -----------------
__global__ void k_zb(const float* __restrict__ W, const float* __restrict__ b) {
    __shared__ __align__(16) float xs[EE];
    {
        const float4* src = (const float4*)(g_X + (SS - 1) * EE);
        float4* dst = (float4*)xs;
        for (int i = threadIdx.x; i < EE / 4; i += blockDim.x) dst[i] = src[i];
    }
    __syncthreads();
    int j = blockIdx.x * 8 + (threadIdx.x >> 5), lane = threadIdx.x & 31;
    const float4* wr4 = (const float4*)(W + (size_t)j * EE);
    const float4* x4 = (const float4*)xs;
    float acc = 0.0f;
#pragma unroll
    for (int i = 0; i < 8; i++) {
        int cq = lane + 32 * i;
        float4 wv = wr4[cq], xv = x4[cq];
        acc = fmaf(wv.x, xv.x, acc); acc = fmaf(wv.y, xv.y, acc);
        acc = fmaf(wv.z, xv.z, acc); acc = fmaf(wv.w, xv.w, acc);
    }
    acc = wredsum(acc);
    if (lane == 0) g_Zb[j] = acc + b[j];
}

// ----------------- fused encoder: all 64 steps, 32 blocks x 512 thr ----------
__global__ void k_enc_all() {
    __shared__ float hT[8 * 64];
    int tid = threadIdx.x;
    int u = blockIdx.x * 16 + (tid >> 5), lane = tid & 31;
    const uint4* WE = (const uint4*)g_Whhf_h;
    for (int t = 0; t < SS; t++) {
        int p = t & 1;
        if (tid < HH)
            hT[(tid & 7) * 64 + (tid >> 3)] = __ldcg(&g_eh[p][tid]);
        __syncthreads();
        float z[4] = {0.f, 0.f, 0.f, 0.f};
#pragma unroll
        for (int i = 0; i < 2; i++) {
            int cq = lane + 32 * i;
            float h[8];
#pragma unroll
            for (int j = 0; j < 8; j++) h[j] = hT[j * 64 + cq];
#pragma unroll
            for (int g = 0; g < 4; g++) {
                uint4 wv = WE[(size_t)(g * HH + u) * 64 + cq];
                fma8s(z[g], wv, h);
            }
        }
#pragma unroll
        for (int g = 0; g < 4; g++) z[g] = wredsum(z[g]);
        if (lane == 0) {
            const float* zx = g_Zf + t * (4 * HH);
            float zi = zx[u] + z[0], zf = zx[HH + u] + z[1];
            float zg = zx[2 * HH + u] + z[2], zo = zx[3 * HH + u] + z[3];
            float c = sigm(zf) * g_ec[u] + sigm(zi) * tanhf(zg);
            g_ec[u] = c;
            g_eh[p ^ 1][u] = sigm(zo) * tanhf(c);
        }
        gridbar(32);
    }
}

// ----------------- backward cell (1 step, h=c=0) + decoder init -----------------
__global__ void k_init2() {
    int u = threadIdx.x;
    if (u < HH) {
        float zi = g_Zb[u], zg = g_Zb[2 * HH + u], zo = g_Zb[3 * HH + u];
        float c = sigm(zi) * tanhf(zg);
        float hb = sigm(zo) * tanhf(c);
        g_sent[u] = g_eh[0][u];
        g_sent[HH + u] = hb;
    }
    __syncthreads();
    for (int d = u; d < DD; d += blockDim.x) {
        float s = g_sent[d];
        g_dh[0][d] = make_float4(s, s, s, s);
        g_dc[0][d] = make_float4(0.f, 0.f, 0.f, 0.f);
    }
    if (u < KKB) {
        g_probs[u] = (u == 0) ? 1.0f : 0.0f;
        g_last[u] = BOSTOK;
        g_fin[u] = 0;
        for (int i = 0; i < TOKL; i++) g_tok[0][u * TOKL + i] = BOSTOK;
    }
}

// ----------------- fused decoder LSTM gates + cat (128 blocks, 1 grid barrier) --
__global__ void k_dec(const float* __restrict__ demb, const float* __restrict__ b,
                      const float* __restrict__ cat_b, int p) {
    __shared__ __align__(16) float4 smA[2048];
    int tid = threadIdx.x;
    int l0 = g_last[0], l1 = g_last[1], l2 = g_last[2], l3 = g_last[3];
    float4* eT = smA;
    float4* hT = smA + 1024;
    for (int a = tid; a < DD; a += blockDim.x) {
        int j = a & 7, cq = a >> 3;
        eT[j * 128 + cq] = make_float4(demb[(size_t)l0 * EE + a], demb[(size_t)l1 * EE + a],
                                       demb[(size_t)l2 * EE + a], demb[(size_t)l3 * EE + a]);
        hT[j * 128 + cq] = g_dh[p][a];
    }
    __syncthreads();
    int u = blockIdx.x * 8 + (tid >> 5), lane = tid & 31;
    const uint4* W1 = (const uint4*)g_Wih_h;
    const uint4* W2 = (const uint4*)g_Whh_h;
    float4 acc[4];
#pragma unroll
    for (int g = 0; g < 4; g++) acc[g] = make_float4(0.f, 0.f, 0.f, 0.f);
#pragma unroll
    for (int i = 0; i < 4; i++) {
        int cq = lane + 32 * i;
        float4 e[8];
#pragma unroll
        for (int j = 0; j < 8; j++) e[j] = eT[j * 128 + cq];
#pragma unroll
        for (int g = 0; g < 4; g++)
            fma8(acc[g], W1[(size_t)(g * DD + u) * 128 + cq], e);
    }
#pragma unroll
    for (int i = 0; i < 4; i++) {
        int cq = lane + 32 * i;
        float4 h[8];
#pragma unroll
        for (int j = 0; j < 8; j++) h[j] = hT[j * 128 + cq];
#pragma unroll
        for (int g = 0; g < 4; g++)
            fma8(acc[g], W2[(size_t)(g * DD + u) * 128 + cq], h);
    }
#pragma unroll
    for (int g = 0; g < 4; g++) redsum4(acc[g]);
    if (lane == 0) {
        float bi = b[u], bf = b[DD + u], bg = b[2 * DD + u], bo = b[3 * DD + u];
        float4 c4 = g_dc[p][u];
        float4 cn, hn;
        cn.x = sigm(acc[1].x + bf) * c4.x + sigm(acc[0].x + bi) * tanhf(acc[2].x + bg);
        cn.y = sigm(acc[1].y + bf) * c4.y + sigm(acc[0].y + bi) * tanhf(acc[2].y + bg);
        cn.z = sigm(acc[1].z + bf) * c4.z + sigm(acc[0].z + bi) * tanhf(acc[2].z + bg);
        cn.w = sigm(acc[1].w + bf) * c4.w + sigm(acc[0].w + bi) * tanhf(acc[2].w + bg);
        hn.x = sigm(acc[3].x + bo) * tanhf(cn.x);
        hn.y = sigm(acc[3].y + bo) * tanhf(cn.y);
        hn.z = sigm(acc[3].z + bo) * tanhf(cn.z);
        hn.w = sigm(acc[3].w + bo) * tanhf(cn.w);
        g_htmp[u] = hn;
        g_ctmp[u] = cn;
    }

    gridbar(128);

    // phase B: outs = tanh([h, emb] @ cat_W^T + cat_b)
    for (int a = tid; a < 2 * DD; a += blockDim.x) {
        int j = a & 7, cq = a >> 3;
        float4 v;
        if (a < DD) v = __ldcg(&g_htmp[a]);
        else {
            int e = a - DD;
            v = make_float4(demb[(size_t)l0 * EE + e], demb[(size_t)l1 * EE + e],
                            demb[(size_t)l2 * EE + e], demb[(size_t)l3 * EE + e]);
        }
        smA[j * 256 + cq] = v;
    }
    __syncthreads();
    const uint4* WC = (const uint4*)g_Wcat_h;
    float4 a4 = make_float4(0.f, 0.f, 0.f, 0.f);
#pragma unroll
    for (int i = 0; i < 8; i++) {
        int cq = lane + 32 * i;
        float4 f[8];
#pragma unroll
        for (int j = 0; j < 8; j++) f[j] = smA[j * 256 + cq];
        fma8(a4, WC[(size_t)u * 256 + cq], f);
    }
    redsum4(a4);
    if (lane == 0) {
        float bd = cat_b[u];
        g_outs[u] = make_float4(tanhf(a4.x + bd), tanhf(a4.y + bd),
                                tanhf(a4.z + bd), tanhf(a4.w + bd));
    }
}

// ----------------- logits: fp16 W, 4 rows/warp for 3 blocks/SM occupancy ------
// grid 1571 x 256; warp owns 4 consecutive rows; block covers 32 rows.
__global__ void __launch_bounds__(256, 3)
k_logits(const float* __restrict__ b) {
    __shared__ __align__(16) float4 oT[DD];   // oT[j*128+cq] = outs[8cq+j]
    __shared__ float4 wmax[8];
    for (int a = threadIdx.x; a < DD; a += blockDim.x) {
        int j = a & 7, cq = a >> 3;
        oT[j * 128 + cq] = g_outs[a];
    }
    __syncthreads();
    int w = threadIdx.x >> 5, lane = threadIdx.x & 31;
    int vbase = blockIdx.x * 32 + w * 4;
    const uint4* W4 = (const uint4*)g_Wout_h;   // row: 1024 halves = 128 uint4
    float4 acc[4];
#pragma unroll
    for (int r = 0; r < 4; r++) acc[r] = make_float4(0.f, 0.f, 0.f, 0.f);
#pragma unroll
    for (int i = 0; i < 4; i++) {
        int cq = lane + 32 * i;
        float4 o[8];
#pragma unroll
        for (int j = 0; j < 8; j++) o[j] = oT[j * 128 + cq];
#pragma unroll
        for (int r = 0; r < 4; r++) {
            int v = vbase + r; if (v >= VV) v = VV - 1;
            uint4 wv = __ldcs(&W4[(size_t)v * 128 + cq]);   // evict-first stream
            fma8(acc[r], wv, o);
        }
    }
    float4 m = make_float4(-INFINITY, -INFINITY, -INFINITY, -INFINITY);
#pragma unroll
    for (int r = 0; r < 4; r++) {
        redsum4(acc[r]);
        int v = vbase + r;
        if (lane == 0 && v < VV) {
            float bb = b[v];
            acc[r].x += bb; acc[r].y += bb; acc[r].z += bb; acc[r].w += bb;
            g_logits4[v] = acc[r];
            m = max4(m, acc[r]);
        }
    }
    if (lane == 0) wmax[w] = m;
    __syncthreads();
    if (threadIdx.x == 0) {
        float4 mm = wmax[0];
#pragma unroll
        for (int i = 1; i < 8; i++) mm = max4(mm, wmax[i]);
        g_bmax4[blockIdx.x] = mm;
    }
}

// ----------------- fused select: expsum + topk + final (64 blocks, 2 barriers) --
__global__ void k_select(int t, int p, float* out, int out_size) {
    __shared__ float4 red[256];
    __shared__ float cv[256][4];
    __shared__ int   ci[256][4];
    __shared__ int parent[4], tokn[4], nfin[4];
    __shared__ float topv[4];
    int tid = threadIdx.x, blk = blockIdx.x;

    // ---- phase 1: global max + per-chunk exp-sum ----
    float4 m = make_float4(-INFINITY, -INFINITY, -INFINITY, -INFINITY);
    for (int i = tid; i < NLB; i += 256) m = max4(m, g_bmax4[i]);
    red[tid] = m; __syncthreads();
    for (int s = 128; s; s >>= 1) {
        if (tid < s) red[tid] = max4(red[tid], red[tid + s]);
        __syncthreads();
    }
    float4 gm = red[0]; __syncthreads();

    float4 sum = make_float4(0.f, 0.f, 0.f, 0.f);
    int base = blk * VCH;
    for (int i = tid; i < VCH; i += 256) {
        int v = base + i;
        if (v >= VV) break;
        float4 l = g_logits4[v];
        sum.x += expf(l.x - gm.x); sum.y += expf(l.y - gm.y);
        sum.z += expf(l.z - gm.z); sum.w += expf(l.w - gm.w);
    }
    red[tid] = sum; __syncthreads();
    for (int s = 128; s; s >>= 1) {
        if (tid < s) red[tid] = add4(red[tid], red[tid + s]);
        __syncthreads();
    }
    if (tid == 0) g_bsum4[blk] = red[0];

    gridbar(NSB);

    // ---- phase 2: global sum + per-chunk top-4 ----
    float4 sm = (tid < NSB) ? __ldcg(&g_bsum4[tid]) : make_float4(0.f, 0.f, 0.f, 0.f);
    red[tid] = sm; __syncthreads();
    for (int s = 128; s; s >>= 1) {
        if (tid < s) red[tid] = add4(red[tid], red[tid + s]);
        __syncthreads();
    }
    float4 tot = red[0]; __syncthreads();

    float pr[4] = {g_probs[0], g_probs[1], g_probs[2], g_probs[3]};
    int   fn[4] = {g_fin[0], g_fin[1], g_fin[2], g_fin[3]};
    float gmk[4] = {gm.x, gm.y, gm.z, gm.w};
    float tk[4]  = {tot.x, tot.y, tot.z, tot.w};

    float lv[4] = {-INFINITY, -INFINITY, -INFINITY, -INFINITY};
    int   li[4] = {INT_MAX, INT_MAX, INT_MAX, INT_MAX};
    for (int i = tid; i < VCH; i += 256) {
        int v = base + i;
        if (v >= VV) break;
        float4 l = g_logits4[v];
        float lk[4] = {l.x, l.y, l.z, l.w};
#pragma unroll
        for (int k = 0; k < 4; k++) {
            float pp = fn[k] ? (v == EOSTOK ? 1.0f : 0.0f)
                             : fdiv_rn(expf(lk[k] - gmk[k]), tk[k]);
            ins4(lv, li, pmul_ftz(pr[k], pp), k * VV + v);  // FTZ: DO NOT CHANGE
        }
    }
#pragma unroll
    for (int k = 0; k < 4; k++) { cv[tid][k] = lv[k]; ci[tid][k] = li[k]; }
    __syncthreads();
    for (int s = 128; s; s >>= 1) {
        if (tid < s) {
            float av[4]; int ai[4];
#pragma unroll
            for (int k = 0; k < 4; k++) { av[k] = cv[tid][k]; ai[k] = ci[tid][k]; }
#pragma unroll
            for (int k = 0; k < 4; k++) ins4(av, ai, cv[tid + s][k], ci[tid + s][k]);
#pragma unroll
            for (int k = 0; k < 4; k++) { cv[tid][k] = av[k]; ci[tid][k] = ai[k]; }
        }
        __syncthreads();
    }
    if (tid == 0) {
#pragma unroll
        for (int k = 0; k < 4; k++) { g_tval[blk * 4 + k] = cv[0][k]; g_tidx[blk * 4 + k] = ci[0][k]; }
    }

    gridbar(NSB);

    if (blk != 0) return;

    // ---- phase 3 (block 0): final merge + beam-state update ----
    if (tid < NSB) {
#pragma unroll
        for (int k = 0; k < 4; k++) {
            cv[tid][k] = __ldcg(&g_tval[tid * 4 + k]);
            ci[tid][k] = __ldcg(&g_tidx[tid * 4 + k]);
        }
    }
    __syncthreads();
    for (int s = 32; s; s >>= 1) {
        if (tid < s) {
            float av[4]; int ai[4];
#pragma unroll
            for (int k = 0; k < 4; k++) { av[k] = cv[tid][k]; ai[k] = ci[tid][k]; }
#pragma unroll
            for (int k = 0; k < 4; k++) ins4(av, ai, cv[tid + s][k], ci[tid + s][k]);
#pragma unroll
            for (int k = 0; k < 4; k++) { cv[tid][k] = av[k]; ci[tid][k] = ai[k]; }
        }
        __syncthreads();
    }
    if (tid == 0) {
        int ofin[4] = {g_fin[0], g_fin[1], g_fin[2], g_fin[3]};
#pragma unroll
        for (int k = 0; k < 4; k++) {
            topv[k] = cv[0][k];
            int idx = ci[0][k];
            parent[k] = idx / VV;
            tokn[k] = idx % VV;
            nfin[k] = ofin[idx / VV] | ((idx % VV) == EOSTOK);
        }
    }
    __syncthreads();

    if (tid < KKB * TOKL) {
        int k = tid / TOKL, i = tid % TOKL;
        int val = (i == t + 1) ? tokn[k] : g_tok[p][parent[k] * TOKL + i];
        g_tok[p ^ 1][k * TOKL + i] = val;
    }
    for (int d = tid; d < DD; d += blockDim.x) {
        float4 h = g_htmp[d], c = g_ctmp[d];
        float hh[4] = {h.x, h.y, h.z, h.w};
        float cc[4] = {c.x, c.y, c.z, c.w};
        g_dh[p ^ 1][d] = make_float4(hh[parent[0]], hh[parent[1]], hh[parent[2]], hh[parent[3]]);
        g_dc[p ^ 1][d] = make_float4(cc[parent[0]], cc[parent[1]], cc[parent[2]], cc[parent[3]]);
    }
    if (tid < KKB) {
        g_probs[tid] = topv[tid];
        g_last[tid] = tokn[tid];
        g_fin[tid] = nfin[tid];
    }
    __syncthreads();

    if (t == MAXLEN - 1 && tid == 0) {
        int best = 0; float bv = topv[0];
        for (int k = 1; k < 4; k++) if (topv[k] > bv) { bv = topv[k]; best = k; }
        if (out_size >= TOKL + KKB) {
            for (int i = 0; i < TOKL; i++) out[i] = (float)g_tok[p ^ 1][best * TOKL + i];
            for (int k = 0; k < KKB; k++) out[TOKL + k] = topv[k];
        } else if (out_size == TOKL) {
            int* io = (int*)out;
            for (int i = 0; i < TOKL; i++) io[i] = g_tok[p ^ 1][best * TOKL + i];
        } else if (out_size == KKB) {
            for (int k = 0; k < KKB; k++) out[k] = topv[k];
        } else {
            int n = out_size < TOKL ? out_size : TOKL;
            for (int i = 0; i < n; i++) out[i] = (float)g_tok[p ^ 1][best * TOKL + i];
        }
    }
}

// ----------------- launch -----------------
extern "C" void kernel_launch(void* const* d_in, const int* in_sizes, int n_in,
                              void* d_out, int out_size) {
    const int*   sent      = (const int*)d_in[0];
    const float* enc_emb   = (const float*)d_in[1];
    const float* enc_Wih_f = (const float*)d_in[2];
    const float* enc_Whh_f = (const float*)d_in[3];
    const float* enc_b_f   = (const float*)d_in[4];
    const float* enc_Wih_b = (const float*)d_in[5];
    /* enc_Whh_b (d_in[6]) unused: backward LSTM only runs 1 step with h=0 */
    const float* enc_b_b   = (const float*)d_in[7];
    const float* dec_emb   = (const float*)d_in[8];
    const float* dec_Wih   = (const float*)d_in[9];
    const float* dec_Whh   = (const float*)d_in[10];
    const float* dec_b     = (const float*)d_in[11];
    const float* cat_W     = (const float*)d_in[12];
    const float* cat_b     = (const float*)d_in[13];
    const float* out_W     = (const float*)d_in[14];
    const float* out_b     = (const float*)d_in[15];
    (void)in_sizes; (void)n_in;

    // fp16 weight conversions (per-call; 4 strided uint4 per thread for MLP)
    {
        int n8, nb;
        n8 = (VV * DD) / 8;      nb = (n8 + 2047) / 2048;  k_cvt_out<<<nb, 512>>>((const float4*)out_W, n8);
        n8 = (4 * DD * EE) / 8;  nb = (n8 + 2047) / 2048;  k_cvt_ih <<<nb, 512>>>((const float4*)dec_Wih, n8);
        n8 = (4 * DD * DD) / 8;  nb = (n8 + 2047) / 2048;  k_cvt_hh <<<nb, 512>>>((const float4*)dec_Whh, n8);
        n8 = (DD * 2 * DD) / 8;  nb = (n8 + 2047) / 2048;  k_cvt_cat<<<nb, 512>>>((const float4*)cat_W, n8);
        n8 = (4 * HH * HH) / 8;  nb = (n8 + 2047) / 2048;  k_cvt_enc<<<nb, 512>>>((const float4*)enc_Whh_f, n8);
    }

    k_init0<<<1, 512>>>();
    k_gather<<<SS, 256>>>(sent, enc_emb);
    k_zxf<<<256, 256>>>(enc_Wih_f, enc_b_f);
    k_zb<<<256, 256>>>(enc_Wih_b, enc_b_b);
    k_enc_all<<<32, 512>>>();
    k_init2<<<1, 512>>>();

    for (int t = 0; t < MAXLEN; t++) {
        int p = t & 1;
        k_dec<<<128, 256>>>(dec_emb, dec_b, cat_b, p);
        k_logits<<<NLB, 256>>>(out_b);
        k_select<<<NSB, 256>>>(t, p, (float*)d_out, out_size);
    }
}

// round 16
// speedup vs baseline: 1.2679x; 1.0360x over previous
#include <cuda_runtime.h>
#include <cuda_fp16.h>
#include <math.h>
#include <limits.h>

#define VV 50257
#define EE 1024
#define HH 512
#define DD 1024
#define SS 64
#define KKB 4
#define MAXLEN 20
#define TOKL (MAXLEN + 1)
#define BOSTOK 1
#define EOSTOK 2
#define NLB 1571         /* logits blocks: 1571*32 >= 50257 (4 rows/warp, 8 warps) */
#define NSB 64           /* select blocks */
#define VCH 786          /* 64*786 >= 50257 */

#define N8_OUT ((size_t)VV * DD / 8)     /* 6432896 */
#define N8_IH  ((size_t)(4 * DD * EE) / 8)
#define N8_HH  ((size_t)(4 * DD * DD) / 8)
#define N8_CAT ((size_t)(DD * 2 * DD) / 8)
#define ENCB 32          /* encoder blocks */
#define CVTB 232         /* converter blocks */

// ----------------- static device scratch (no allocation) -----------------
static __device__ __align__(16) float  g_X[SS * EE];
static __device__ __align__(16) float  g_Zf[SS * 4 * HH];
static __device__ __align__(16) float  g_Zb[4 * HH];
static __device__ __align__(16) float  g_eh[2][HH];
static __device__ __align__(16) float  g_ec[HH];
static __device__ __align__(16) float  g_sent[DD];
static __device__ float4 g_dh[2][DD];
static __device__ float4 g_dc[2][DD];
static __device__ float4 g_htmp[DD];
static __device__ float4 g_ctmp[DD];
static __device__ float4 g_outs[DD];
static __device__ float4 g_logits4[VV];
static __device__ float4 g_bmax4[NLB];
static __device__ float4 g_bsum4[NSB];
static __device__ float  g_tval[NSB * 4];
static __device__ int    g_tidx[NSB * 4];
static __device__ float  g_probs[KKB];
static __device__ int    g_last[KKB];
static __device__ int    g_fin[KKB];
static __device__ int    g_tok[2][KKB * TOKL];

// fp16 weight copies (converted once per kernel_launch call)
static __device__ __align__(16) __half g_Wout_h[(size_t)VV * DD];   // 103 MB
static __device__ __align__(16) __half g_Wih_h[4 * DD * EE];
static __device__ __align__(16) __half g_Whh_h[4 * DD * DD];
static __device__ __align__(16) __half g_Wcat_h[DD * 2 * DD];
static __device__ __align__(16) __half g_Whhf_h[4 * HH * HH];

// ----------------- software grid barrier (sense-reversing, self-resetting) ---
static __device__ unsigned g_barcnt = 0;
static __device__ unsigned g_bargen = 0;
__device__ __forceinline__ void gridbar(unsigned nblk) {
    __syncthreads();
    if (threadIdx.x == 0) {
        __threadfence();
        unsigned gen = atomicAdd(&g_bargen, 0u);      // read epoch BEFORE arriving
        if (atomicAdd(&g_barcnt, 1u) == nblk - 1) {
            atomicExch(&g_barcnt, 0u);
            __threadfence();
            atomicAdd(&g_bargen, 1u);
        } else {
            while (atomicAdd(&g_bargen, 0u) == gen) { __nanosleep(32); }
        }
        __threadfence();
    }
    __syncthreads();
}

// ----------------- controlled-precision scalar ops (LOAD-BEARING) -----------
// FTZ multiply for the beam-prob candidate product: the reference runtime
// flushes subnormal results to zero (verified round 5: rel_err == 0).
__device__ __forceinline__ float pmul_ftz(float a, float b) {
    float r;
    asm("mul.rn.ftz.f32 %0, %1, %2;" : "=f"(r) : "f"(a), "f"(b));
    return r;
}
__device__ __forceinline__ float fdiv_rn(float a, float b) {
    float r;
    asm("div.rn.f32 %0, %1, %2;" : "=f"(r) : "f"(a), "f"(b));
    return r;
}

// ----------------- helpers -----------------
__device__ __forceinline__ float sigm(float x) { return 1.0f / (1.0f + expf(-x)); }
__device__ __forceinline__ float wredsum(float v) {
#pragma unroll
    for (int o = 16; o; o >>= 1) v += __shfl_xor_sync(0xffffffffu, v, o);
    return v;
}
__device__ __forceinline__ float4 max4(float4 a, float4 b) {
    return make_float4(fmaxf(a.x, b.x), fmaxf(a.y, b.y), fmaxf(a.z, b.z), fmaxf(a.w, b.w));
}
__device__ __forceinline__ float4 add4(float4 a, float4 b) {
    return make_float4(a.x + b.x, a.y + b.y, a.z + b.z, a.w + b.w);
}
__device__ __forceinline__ void fma4(float4& a, float w, float4 x) {
    a.x = fmaf(w, x.x, a.x); a.y = fmaf(w, x.y, a.y);
    a.z = fmaf(w, x.z, a.z); a.w = fmaf(w, x.w, a.w);
}
__device__ __forceinline__ void redsum4(float4& a) {
    a.x = wredsum(a.x); a.y = wredsum(a.y); a.z = wredsum(a.z); a.w = wredsum(a.w);
}
// 8 fp16 weights (one uint4) against 8 beam-float4 activations
__device__ __forceinline__ void fma8(float4& acc, uint4 wv, const float4* o) {
    __half2 h;
    h = *(__half2*)&wv.x; fma4(acc, __low2float(h), o[0]); fma4(acc, __high2float(h), o[1]);
    h = *(__half2*)&wv.y; fma4(acc, __low2float(h), o[2]); fma4(acc, __high2float(h), o[3]);
    h = *(__half2*)&wv.z; fma4(acc, __low2float(h), o[4]); fma4(acc, __high2float(h), o[5]);
    h = *(__half2*)&wv.w; fma4(acc, __low2float(h), o[6]); fma4(acc, __high2float(h), o[7]);
}
__device__ __forceinline__ void fma8s(float& acc, uint4 wv, const float* h) {
    __half2 x;
    x = *(__half2*)&wv.x; acc = fmaf(__low2float(x), h[0], acc); acc = fmaf(__high2float(x), h[1], acc);
    x = *(__half2*)&wv.y; acc = fmaf(__low2float(x), h[2], acc); acc = fmaf(__high2float(x), h[3], acc);
    x = *(__half2*)&wv.z; acc = fmaf(__low2float(x), h[4], acc); acc = fmaf(__high2float(x), h[5], acc);
    x = *(__half2*)&wv.w; acc = fmaf(__low2float(x), h[6], acc); acc = fmaf(__high2float(x), h[7], acc);
}

// top-k comparator: larger value wins; tie -> smaller flat index (JAX top_k)
__device__ __forceinline__ bool cgt(float v1, int i1, float v2, int i2) {
    return (v1 > v2) || (v1 == v2 && i1 < i2);
}
__device__ __forceinline__ void ins4(float* lv, int* li, float v, int idx) {
    if (!cgt(v, idx, lv[3], li[3])) return;
    lv[3] = v; li[3] = idx;
#pragma unroll
    for (int j = 3; j > 0; j--) {
        if (cgt(lv[j], li[j], lv[j - 1], li[j - 1])) {
            float tv = lv[j]; lv[j] = lv[j - 1]; lv[j - 1] = tv;
            int ti = li[j]; li[j] = li[j - 1]; li[j - 1] = ti;
        } else break;
    }
}

// ----------------- fp32 -> fp16 conversion helpers --------------------------
__device__ __forceinline__ uint4 cvt8h(float4 v0, float4 v1) {
    __half2 a = __floats2half2_rn(v0.x, v0.y);
    __half2 b = __floats2half2_rn(v0.z, v0.w);
    __half2 c = __floats2half2_rn(v1.x, v1.y);
    __half2 d = __floats2half2_rn(v1.z, v1.w);
    return make_uint4(*(unsigned*)&a, *(unsigned*)&b, *(unsigned*)&c, *(unsigned*)&d);
}
__device__ __forceinline__ void cvt_range(const float4* __restrict__ src, __half* dst,
                                          size_t n8, size_t start, size_t stride) {
    for (size_t i = start; i < n8; i += stride) {
        float4 a = __ldcs(&src[2 * i]);
        float4 b = __ldcs(&src[2 * i + 1]);
        __stcs(&((uint4*)dst)[i], cvt8h(a, b));
    }
}

// standalone cvt for enc_Whh_f (must precede the fused encoder kernel)
__global__ void k_cvt_enc(const float4* __restrict__ src, int n8) {
    unsigned s = gridDim.x * blockDim.x;
    unsigned i0 = blockIdx.x * blockDim.x + threadIdx.x;
    for (unsigned i = i0; i < (unsigned)n8; i += s) {
        float4 a = __ldcs(&src[2 * (size_t)i]);
        float4 b = __ldcs(&src[2 * (size_t)i + 1]);
        ((uint4*)g_Whhf_h)[i] = cvt8h(a, b);
    }
}

// ----------------- init: zero encoder state -----------------
__global__ void k_init0() {
    int u = threadIdx.x;
    if (u < HH) { g_eh[0][u] = 0.0f; g_eh[1][u] = 0.0f; g_ec[u] = 0.0f; }
}

// ----------------- gather embedded sentence -----------------
__global__ void k_gather(const int* __restrict__ sent, const float* __restrict__ emb) {
    int t = blockIdx.x;
    const float4* src = (const float4*)(emb + (size_t)sent[t] * EE);
    float4* dst = (float4*)(g_X + t * EE);
    for (int e = threadIdx.x; e < EE / 4; e += blockDim.x) dst[e] = src[e];
}

// ----------------- Zx_f = X @ Wih_f^T + b (fp32, one-time) -----------------
__global__ void k_zxf(const float* __restrict__ W, const float* __restrict__ b) {
    __shared__ __align__(16) float xs[8 * EE];
    int w = threadIdx.x >> 5, lane = threadIdx.x & 31;
    int j = blockIdx.x * 8 + w;
    const float4* wr4 = (const float4*)(W + (size_t)j * EE);
    float bj = b[j];
    for (int tc = 0; tc < 8; tc++) {
        __syncthreads();
        {
            const float4* src = (const float4*)(g_X + tc * 8 * EE);
            float4* dst = (float4*)xs;
            for (int i = threadIdx.x; i < 8 * EE / 4; i += blockDim.x) dst[i] = src[i];
        }
        __syncthreads();
        for (int tt = 0; tt < 8; tt++) {
            float acc = 0.0f;
            const float4* x4 = (const float4*)(xs + tt * EE);
#pragma unroll
            for (int i = 0; i < 8; i++) {
                int cq = lane + 32 * i;
                float4 wv = wr4[cq], xv = x4[cq];
                acc = fmaf(wv.x, xv.x, acc); acc = fmaf(wv.y, xv.y, acc);
                acc = fmaf(wv.z, xv.z, acc); acc = fmaf(wv.w, xv.w, acc);
            }
            acc = wredsum(acc);
            if (lane == 0) g_Zf[(tc * 8 + tt) * (4 * HH) + j] = acc + bj;
        }
    }
}

// ----------------- Zb = x_last @ Wih_b^T + b_b (fp32, one-time) -----------------
__global__ void k_zb(const float* __restrict__ W, const float* __restrict__ b) {
    __shared__ __align__(16) float xs[EE];
    {
        const float4* src = (const float4*)(g_X + (SS - 1) * EE);
        float4* dst = (float4*)xs;
        for (int i = threadIdx.x; i < EE / 4; i += blockDim.x) dst[i] = src[i];
    }
    __syncthreads();
    int j = blockIdx.x * 8 + (threadIdx.x >> 5), lane = threadIdx.x & 31;
    const float4* wr4 = (const float4*)(W + (size_t)j * EE);
    const float4* x4 = (const float4*)xs;
    float acc = 0.0f;
#pragma unroll
    for (int i = 0; i < 8; i++) {
        int cq = lane + 32 * i;
        float4 wv = wr4[cq], xv = x4[cq];
        acc = fmaf(wv.x, xv.x, acc); acc = fmaf(wv.y, xv.y, acc);
        acc = fmaf(wv.z, xv.z, acc); acc = fmaf(wv.w, xv.w, acc);
    }
    acc = wredsum(acc);
    if (lane == 0) g_Zb[j] = acc + b[j];
}

// ===== fused: encoder (blocks 0..31, 64 steps, 32-block barrier) +
//              fp16 conversion of decode weights (blocks 32..263, grid-stride) =====
__global__ void __launch_bounds__(512, 2)
k_enc_cvt(const float4* __restrict__ Wout32, const float4* __restrict__ Wih32,
          const float4* __restrict__ Whh32, const float4* __restrict__ Wcat32) {
    if (blockIdx.x >= ENCB) {
        // converter role: stream out_W / Wih / Whh / cat_W fp32 -> fp16
        size_t start = (size_t)(blockIdx.x - ENCB) * blockDim.x + threadIdx.x;
        size_t stride = (size_t)CVTB * blockDim.x;
        cvt_range(Wout32, g_Wout_h, N8_OUT, start, stride);
        cvt_range(Wih32,  g_Wih_h,  N8_IH,  start, stride);
        cvt_range(Whh32,  g_Whh_h,  N8_HH,  start, stride);
        cvt_range(Wcat32, g_Wcat_h, N8_CAT, start, stride);
        return;
    }
    // encoder role (identical to the R15-verified k_enc_all)
    __shared__ float hT[8 * 64];
    int tid = threadIdx.x;
    int u = blockIdx.x * 16 + (tid >> 5), lane = tid & 31;
    const uint4* WE = (const uint4*)g_Whhf_h;
    for (int t = 0; t < SS; t++) {
        int p = t & 1;
        if (tid < HH)
            hT[(tid & 7) * 64 + (tid >> 3)] = __ldcg(&g_eh[p][tid]);
        __syncthreads();
        float z[4] = {0.f, 0.f, 0.f, 0.f};
#pragma unroll
        for (int i = 0; i < 2; i++) {
            int cq = lane + 32 * i;
            float h[8];
#pragma unroll
            for (int j = 0; j < 8; j++) h[j] = hT[j * 64 + cq];
#pragma unroll
            for (int g = 0; g < 4; g++) {
                uint4 wv = WE[(size_t)(g * HH + u) * 64 + cq];
                fma8s(z[g], wv, h);
            }
        }
#pragma unroll
        for (int g = 0; g < 4; g++) z[g] = wredsum(z[g]);
        if (lane == 0) {
            const float* zx = g_Zf + t * (4 * HH);
            float zi = zx[u] + z[0], zf = zx[HH + u] + z[1];
            float zg = zx[2 * HH + u] + z[2], zo = zx[3 * HH + u] + z[3];
            float c = sigm(zf) * g_ec[u] + sigm(zi) * tanhf(zg);
            g_ec[u] = c;
            g_eh[p ^ 1][u] = sigm(zo) * tanhf(c);
        }
        gridbar(ENCB);   // converter blocks never touch these counters
    }
}

// ----------------- backward cell (1 step, h=c=0) + decoder init -----------------
__global__ void k_init2() {
    int u = threadIdx.x;
    if (u < HH) {
        float zi = g_Zb[u], zg = g_Zb[2 * HH + u], zo = g_Zb[3 * HH + u];
        float c = sigm(zi) * tanhf(zg);
        float hb = sigm(zo) * tanhf(c);
        g_sent[u] = g_eh[0][u];
        g_sent[HH + u] = hb;
    }
    __syncthreads();
    for (int d = u; d < DD; d += blockDim.x) {
        float s = g_sent[d];
        g_dh[0][d] = make_float4(s, s, s, s);
        g_dc[0][d] = make_float4(0.f, 0.f, 0.f, 0.f);
    }
    if (u < KKB) {
        g_probs[u] = (u == 0) ? 1.0f : 0.0f;
        g_last[u] = BOSTOK;
        g_fin[u] = 0;
        for (int i = 0; i < TOKL; i++) g_tok[0][u * TOKL + i] = BOSTOK;
    }
}

// ----------------- fused decoder LSTM gates + cat (128 blocks, 1 grid barrier) --
__global__ void k_dec(const float* __restrict__ demb, const float* __restrict__ b,
                      const float* __restrict__ cat_b, int p) {
    __shared__ __align__(16) float4 smA[2048];
    int tid = threadIdx.x;
    int l0 = g_last[0], l1 = g_last[1], l2 = g_last[2], l3 = g_last[3];
    float4* eT = smA;
    float4* hT = smA + 1024;
    for (int a = tid; a < DD; a += blockDim.x) {
        int j = a & 7, cq = a >> 3;
        eT[j * 128 + cq] = make_float4(demb[(size_t)l0 * EE + a], demb[(size_t)l1 * EE + a],
                                       demb[(size_t)l2 * EE + a], demb[(size_t)l3 * EE + a]);
        hT[j * 128 + cq] = g_dh[p][a];
    }
    __syncthreads();
    int u = blockIdx.x * 8 + (tid >> 5), lane = tid & 31;
    const uint4* W1 = (const uint4*)g_Wih_h;
    const uint4* W2 = (const uint4*)g_Whh_h;
    float4 acc[4];
#pragma unroll
    for (int g = 0; g < 4; g++) acc[g] = make_float4(0.f, 0.f, 0.f, 0.f);
#pragma unroll
    for (int i = 0; i < 4; i++) {
        int cq = lane + 32 * i;
        float4 e[8];
#pragma unroll
        for (int j = 0; j < 8; j++) e[j] = eT[j * 128 + cq];
#pragma unroll
        for (int g = 0; g < 4; g++)
            fma8(acc[g], W1[(size_t)(g * DD + u) * 128 + cq], e);
    }
#pragma unroll
    for (int i = 0; i < 4; i++) {
        int cq = lane + 32 * i;
        float4 h[8];
#pragma unroll
        for (int j = 0; j < 8; j++) h[j] = hT[j * 128 + cq];
#pragma unroll
        for (int g = 0; g < 4; g++)
            fma8(acc[g], W2[(size_t)(g * DD + u) * 128 + cq], h);
    }
#pragma unroll
    for (int g = 0; g < 4; g++) redsum4(acc[g]);
    if (lane == 0) {
        float bi = b[u], bf = b[DD + u], bg = b[2 * DD + u], bo = b[3 * DD + u];
        float4 c4 = g_dc[p][u];
        float4 cn, hn;
        cn.x = sigm(acc[1].x + bf) * c4.x + sigm(acc[0].x + bi) * tanhf(acc[2].x + bg);
        cn.y = sigm(acc[1].y + bf) * c4.y + sigm(acc[0].y + bi) * tanhf(acc[2].y + bg);
        cn.z = sigm(acc[1].z + bf) * c4.z + sigm(acc[0].z + bi) * tanhf(acc[2].z + bg);
        cn.w = sigm(acc[1].w + bf) * c4.w + sigm(acc[0].w + bi) * tanhf(acc[2].w + bg);
        hn.x = sigm(acc[3].x + bo) * tanhf(cn.x);
        hn.y = sigm(acc[3].y + bo) * tanhf(cn.y);
        hn.z = sigm(acc[3].z + bo) * tanhf(cn.z);
        hn.w = sigm(acc[3].w + bo) * tanhf(cn.w);
        g_htmp[u] = hn;
        g_ctmp[u] = cn;
    }

    gridbar(128);

    // phase B: outs = tanh([h, emb] @ cat_W^T + cat_b)
    for (int a = tid; a < 2 * DD; a += blockDim.x) {
        int j = a & 7, cq = a >> 3;
        float4 v;
        if (a < DD) v = __ldcg(&g_htmp[a]);
        else {
            int e = a - DD;
            v = make_float4(demb[(size_t)l0 * EE + e], demb[(size_t)l1 * EE + e],
                            demb[(size_t)l2 * EE + e], demb[(size_t)l3 * EE + e]);
        }
        smA[j * 256 + cq] = v;
    }
    __syncthreads();
    const uint4* WC = (const uint4*)g_Wcat_h;
    float4 a4 = make_float4(0.f, 0.f, 0.f, 0.f);
#pragma unroll
    for (int i = 0; i < 8; i++) {
        int cq = lane + 32 * i;
        float4 f[8];
#pragma unroll
        for (int j = 0; j < 8; j++) f[j] = smA[j * 256 + cq];
        fma8(a4, WC[(size_t)u * 256 + cq], f);
    }
    redsum4(a4);
    if (lane == 0) {
        float bd = cat_b[u];
        g_outs[u] = make_float4(tanhf(a4.x + bd), tanhf(a4.y + bd),
                                tanhf(a4.z + bd), tanhf(a4.w + bd));
    }
}

// ----------------- logits: fp16 W, 4 rows/warp, 3 blocks/SM -------------------
__global__ void __launch_bounds__(256, 3)
k_logits(const float* __restrict__ b) {
    __shared__ __align__(16) float4 oT[DD];
    __shared__ float4 wmax[8];
    for (int a = threadIdx.x; a < DD; a += blockDim.x) {
        int j = a & 7, cq = a >> 3;
        oT[j * 128 + cq] = g_outs[a];
    }
    __syncthreads();
    int w = threadIdx.x >> 5, lane = threadIdx.x & 31;
    int vbase = blockIdx.x * 32 + w * 4;
    const uint4* W4 = (const uint4*)g_Wout_h;
    float4 acc[4];
#pragma unroll
    for (int r = 0; r < 4; r++) acc[r] = make_float4(0.f, 0.f, 0.f, 0.f);
#pragma unroll
    for (int i = 0; i < 4; i++) {
        int cq = lane + 32 * i;
        float4 o[8];
#pragma unroll
        for (int j = 0; j < 8; j++) o[j] = oT[j * 128 + cq];
#pragma unroll
        for (int r = 0; r < 4; r++) {
            int v = vbase + r; if (v >= VV) v = VV - 1;
            uint4 wv = __ldcs(&W4[(size_t)v * 128 + cq]);
            fma8(acc[r], wv, o);
        }
    }
    float4 m = make_float4(-INFINITY, -INFINITY, -INFINITY, -INFINITY);
#pragma unroll
    for (int r = 0; r < 4; r++) {
        redsum4(acc[r]);
        int v = vbase + r;
        if (lane == 0 && v < VV) {
            float bb = b[v];
            acc[r].x += bb; acc[r].y += bb; acc[r].z += bb; acc[r].w += bb;
            g_logits4[v] = acc[r];
            m = max4(m, acc[r]);
        }
    }
    if (lane == 0) wmax[w] = m;
    __syncthreads();
    if (threadIdx.x == 0) {
        float4 mm = wmax[0];
#pragma unroll
        for (int i = 1; i < 8; i++) mm = max4(mm, wmax[i]);
        g_bmax4[blockIdx.x] = mm;
    }
}

// ----------------- fused select: expsum + topk + final (64 blocks, 2 barriers) --
__global__ void k_select(int t, int p, float* out, int out_size) {
    __shared__ float4 red[256];
    __shared__ float cv[256][4];
    __shared__ int   ci[256][4];
    __shared__ int parent[4], tokn[4], nfin[4];
    __shared__ float topv[4];
    int tid = threadIdx.x, blk = blockIdx.x;

    float4 m = make_float4(-INFINITY, -INFINITY, -INFINITY, -INFINITY);
    for (int i = tid; i < NLB; i += 256) m = max4(m, g_bmax4[i]);
    red[tid] = m; __syncthreads();
    for (int s = 128; s; s >>= 1) {
        if (tid < s) red[tid] = max4(red[tid], red[tid + s]);
        __syncthreads();
    }
    float4 gm = red[0]; __syncthreads();

    float4 sum = make_float4(0.f, 0.f, 0.f, 0.f);
    int base = blk * VCH;
    for (int i = tid; i < VCH; i += 256) {
        int v = base + i;
        if (v >= VV) break;
        float4 l = g_logits4[v];
        sum.x += expf(l.x - gm.x); sum.y += expf(l.y - gm.y);
        sum.z += expf(l.z - gm.z); sum.w += expf(l.w - gm.w);
    }
    red[tid] = sum; __syncthreads();
    for (int s = 128; s; s >>= 1) {
        if (tid < s) red[tid] = add4(red[tid], red[tid + s]);
        __syncthreads();
    }
    if (tid == 0) g_bsum4[blk] = red[0];

    gridbar(NSB);

    float4 sm = (tid < NSB) ? __ldcg(&g_bsum4[tid]) : make_float4(0.f, 0.f, 0.f, 0.f);
    red[tid] = sm; __syncthreads();
    for (int s = 128; s; s >>= 1) {
        if (tid < s) red[tid] = add4(red[tid], red[tid + s]);
        __syncthreads();
    }
    float4 tot = red[0]; __syncthreads();

    float pr[4] = {g_probs[0], g_probs[1], g_probs[2], g_probs[3]};
    int   fn[4] = {g_fin[0], g_fin[1], g_fin[2], g_fin[3]};
    float gmk[4] = {gm.x, gm.y, gm.z, gm.w};
    float tk[4]  = {tot.x, tot.y, tot.z, tot.w};

    float lv[4] = {-INFINITY, -INFINITY, -INFINITY, -INFINITY};
    int   li[4] = {INT_MAX, INT_MAX, INT_MAX, INT_MAX};
    for (int i = tid; i < VCH; i += 256) {
        int v = base + i;
        if (v >= VV) break;
        float4 l = g_logits4[v];
        float lk[4] = {l.x, l.y, l.z, l.w};
#pragma unroll
        for (int k = 0; k < 4; k++) {
            float pp = fn[k] ? (v == EOSTOK ? 1.0f : 0.0f)
                             : fdiv_rn(expf(lk[k] - gmk[k]), tk[k]);
            ins4(lv, li, pmul_ftz(pr[k], pp), k * VV + v);  // FTZ: DO NOT CHANGE
        }
    }
#pragma unroll
    for (int k = 0; k < 4; k++) { cv[tid][k] = lv[k]; ci[tid][k] = li[k]; }
    __syncthreads();
    for (int s = 128; s; s >>= 1) {
        if (tid < s) {
            float av[4]; int ai[4];
#pragma unroll
            for (int k = 0; k < 4; k++) { av[k] = cv[tid][k]; ai[k] = ci[tid][k]; }
#pragma unroll
            for (int k = 0; k < 4; k++) ins4(av, ai, cv[tid + s][k], ci[tid + s][k]);
#pragma unroll
            for (int k = 0; k < 4; k++) { cv[tid][k] = av[k]; ci[tid][k] = ai[k]; }
        }
        __syncthreads();
    }
    if (tid == 0) {
#pragma unroll
        for (int k = 0; k < 4; k++) { g_tval[blk * 4 + k] = cv[0][k]; g_tidx[blk * 4 + k] = ci[0][k]; }
    }

    gridbar(NSB);

    if (blk != 0) return;

    if (tid < NSB) {
#pragma unroll
        for (int k = 0; k < 4; k++) {
            cv[tid][k] = __ldcg(&g_tval[tid * 4 + k]);
            ci[tid][k] = __ldcg(&g_tidx[tid * 4 + k]);
        }
    }
    __syncthreads();
    for (int s = 32; s; s >>= 1) {
        if (tid < s) {
            float av[4]; int ai[4];
#pragma unroll
            for (int k = 0; k < 4; k++) { av[k] = cv[tid][k]; ai[k] = ci[tid][k]; }
#pragma unroll
            for (int k = 0; k < 4; k++) ins4(av, ai, cv[tid + s][k], ci[tid + s][k]);
#pragma unroll
            for (int k = 0; k < 4; k++) { cv[tid][k] = av[k]; ci[tid][k] = ai[k]; }
        }
        __syncthreads();
    }
    if (tid == 0) {
        int ofin[4] = {g_fin[0], g_fin[1], g_fin[2], g_fin[3]};
#pragma unroll
        for (int k = 0; k < 4; k++) {
            topv[k] = cv[0][k];
            int idx = ci[0][k];
            parent[k] = idx / VV;
            tokn[k] = idx % VV;
            nfin[k] = ofin[idx / VV] | ((idx % VV) == EOSTOK);
        }
    }
    __syncthreads();

    if (tid < KKB * TOKL) {
        int k = tid / TOKL, i = tid % TOKL;
        int val = (i == t + 1) ? tokn[k] : g_tok[p][parent[k] * TOKL + i];
        g_tok[p ^ 1][k * TOKL + i] = val;
    }
    for (int d = tid; d < DD; d += blockDim.x) {
        float4 h = g_htmp[d], c = g_ctmp[d];
        float hh[4] = {h.x, h.y, h.z, h.w};
        float cc[4] = {c.x, c.y, c.z, c.w};
        g_dh[p ^ 1][d] = make_float4(hh[parent[0]], hh[parent[1]], hh[parent[2]], hh[parent[3]]);
        g_dc[p ^ 1][d] = make_float4(cc[parent[0]], cc[parent[1]], cc[parent[2]], cc[parent[3]]);
    }
    if (tid < KKB) {
        g_probs[tid] = topv[tid];
        g_last[tid] = tokn[tid];
        g_fin[tid] = nfin[tid];
    }
    __syncthreads();

    if (t == MAXLEN - 1 && tid == 0) {
        int best = 0; float bv = topv[0];
        for (int k = 1; k < 4; k++) if (topv[k] > bv) { bv = topv[k]; best = k; }
        if (out_size >= TOKL + KKB) {
            for (int i = 0; i < TOKL; i++) out[i] = (float)g_tok[p ^ 1][best * TOKL + i];
            for (int k = 0; k < KKB; k++) out[TOKL + k] = topv[k];
        } else if (out_size == TOKL) {
            int* io = (int*)out;
            for (int i = 0; i < TOKL; i++) io[i] = g_tok[p ^ 1][best * TOKL + i];
        } else if (out_size == KKB) {
            for (int k = 0; k < KKB; k++) out[k] = topv[k];
        } else {
            int n = out_size < TOKL ? out_size : TOKL;
            for (int i = 0; i < n; i++) out[i] = (float)g_tok[p ^ 1][best * TOKL + i];
        }
    }
}

// ----------------- launch -----------------
extern "C" void kernel_launch(void* const* d_in, const int* in_sizes, int n_in,
                              void* d_out, int out_size) {
    const int*   sent      = (const int*)d_in[0];
    const float* enc_emb   = (const float*)d_in[1];
    const float* enc_Wih_f = (const float*)d_in[2];
    const float* enc_Whh_f = (const float*)d_in[3];
    const float* enc_b_f   = (const float*)d_in[4];
    const float* enc_Wih_b = (const float*)d_in[5];
    /* enc_Whh_b (d_in[6]) unused: backward LSTM only runs 1 step with h=0 */
    const float* enc_b_b   = (const float*)d_in[7];
    const float* dec_emb   = (const float*)d_in[8];
    const float* dec_Wih   = (const float*)d_in[9];
    const float* dec_Whh   = (const float*)d_in[10];
    const float* dec_b     = (const float*)d_in[11];
    const float* cat_W     = (const float*)d_in[12];
    const float* cat_b     = (const float*)d_in[13];
    const float* out_W     = (const float*)d_in[14];
    const float* out_b     = (const float*)d_in[15];
    (void)in_sizes; (void)n_in;

    k_init0<<<1, 512>>>();
    k_gather<<<SS, 256>>>(sent, enc_emb);
    {
        int n8 = (4 * HH * HH) / 8;
        k_cvt_enc<<<148, 512>>>((const float4*)enc_Whh_f, n8);   // enc weights first
    }
    k_zxf<<<256, 256>>>(enc_Wih_f, enc_b_f);
    k_zb<<<256, 256>>>(enc_Wih_b, enc_b_b);
    // fused: 32 encoder blocks + 232 converter blocks (decode weights hidden
    // under the sequential encoder's shadow)
    k_enc_cvt<<<ENCB + CVTB, 512>>>((const float4*)out_W, (const float4*)dec_Wih,
                                    (const float4*)dec_Whh, (const float4*)cat_W);
    k_init2<<<1, 512>>>();

    for (int t = 0; t < MAXLEN; t++) {
        int p = t & 1;
        k_dec<<<128, 256>>>(dec_emb, dec_b, cat_b, p);
        k_logits<<<NLB, 256>>>(out_b);
        k_select<<<NSB, 256>>>(t, p, (float*)d_out, out_size);
    }
}

// round 17
// speedup vs baseline: 1.4095x; 1.1117x over previous
#include <cuda_runtime.h>
#include <cuda_fp16.h>
#include <math.h>
#include <limits.h>

#define VV 50257
#define EE 1024
#define HH 512
#define DD 1024
#define SS 64
#define KKB 4
#define MAXLEN 20
#define TOKL (MAXLEN + 1)
#define BOSTOK 1
#define EOSTOK 2
#define NPB 444          /* persistent logits blocks: 3/SM x 148 */
#define NGRP 1571        /* 32-row groups: 1571*32 >= 50257 */
#define NSB 64           /* select blocks */
#define VCH 786          /* 64*786 >= 50257 */

#define N8_OUT ((size_t)VV * DD / 8)
#define N8_IH  ((size_t)(4 * DD * EE) / 8)
#define N8_HH  ((size_t)(4 * DD * DD) / 8)
#define N8_CAT ((size_t)(DD * 2 * DD) / 8)
#define ENCB 32
#define CVTB 232

// ----------------- static device scratch (no allocation) -----------------
static __device__ __align__(16) float  g_X[SS * EE];
static __device__ __align__(16) float  g_Zf[SS * 4 * HH];
static __device__ __align__(16) float  g_Zb[4 * HH];
static __device__ __align__(16) float  g_eh[2][HH];
static __device__ __align__(16) float  g_ec[HH];
static __device__ __align__(16) float  g_sent[DD];
static __device__ float4 g_dh[2][DD];
static __device__ float4 g_dc[2][DD];
static __device__ float4 g_htmp[DD];
static __device__ float4 g_ctmp[DD];
static __device__ float4 g_outs[DD];
static __device__ float4 g_logits4[VV];
static __device__ float4 g_bmax4[NPB];
static __device__ float4 g_bsum4[NSB];
static __device__ float  g_tval[NSB * 4];
static __device__ int    g_tidx[NSB * 4];
static __device__ float  g_probs[KKB];
static __device__ int    g_last[KKB];
static __device__ int    g_fin[KKB];
static __device__ int    g_tok[2][KKB * TOKL];
static __device__ unsigned g_rowctr = 0;   // logits work-steal counter

// fp16 weight copies (converted once per kernel_launch call)
static __device__ __align__(16) __half g_Wout_h[(size_t)VV * DD];   // 103 MB
static __device__ __align__(16) __half g_Wih_h[4 * DD * EE];
static __device__ __align__(16) __half g_Whh_h[4 * DD * DD];
static __device__ __align__(16) __half g_Wcat_h[DD * 2 * DD];
static __device__ __align__(16) __half g_Whhf_h[4 * HH * HH];

// ----------------- software grid barrier (sense-reversing, self-resetting) ---
static __device__ unsigned g_barcnt = 0;
static __device__ unsigned g_bargen = 0;
__device__ __forceinline__ void gridbar(unsigned nblk) {
    __syncthreads();
    if (threadIdx.x == 0) {
        __threadfence();
        unsigned gen = atomicAdd(&g_bargen, 0u);
        if (atomicAdd(&g_barcnt, 1u) == nblk - 1) {
            atomicExch(&g_barcnt, 0u);
            __threadfence();
            atomicAdd(&g_bargen, 1u);
        } else {
            while (atomicAdd(&g_bargen, 0u) == gen) { __nanosleep(32); }
        }
        __threadfence();
    }
    __syncthreads();
}

// ----------------- controlled-precision scalar ops (LOAD-BEARING) -----------
// FTZ multiply for the beam-prob candidate product: the reference runtime
// flushes subnormal results to zero (verified round 5: rel_err == 0).
__device__ __forceinline__ float pmul_ftz(float a, float b) {
    float r;
    asm("mul.rn.ftz.f32 %0, %1, %2;" : "=f"(r) : "f"(a), "f"(b));
    return r;
}
__device__ __forceinline__ float fdiv_rn(float a, float b) {
    float r;
    asm("div.rn.f32 %0, %1, %2;" : "=f"(r) : "f"(a), "f"(b));
    return r;
}

// ----------------- helpers -----------------
__device__ __forceinline__ float sigm(float x) { return 1.0f / (1.0f + expf(-x)); }
__device__ __forceinline__ float wredsum(float v) {
#pragma unroll
    for (int o = 16; o; o >>= 1) v += __shfl_xor_sync(0xffffffffu, v, o);
    return v;
}
__device__ __forceinline__ float4 max4(float4 a, float4 b) {
    return make_float4(fmaxf(a.x, b.x), fmaxf(a.y, b.y), fmaxf(a.z, b.z), fmaxf(a.w, b.w));
}
__device__ __forceinline__ float4 add4(float4 a, float4 b) {
    return make_float4(a.x + b.x, a.y + b.y, a.z + b.z, a.w + b.w);
}
__device__ __forceinline__ void fma4(float4& a, float w, float4 x) {
    a.x = fmaf(w, x.x, a.x); a.y = fmaf(w, x.y, a.y);
    a.z = fmaf(w, x.z, a.z); a.w = fmaf(w, x.w, a.w);
}
__device__ __forceinline__ void redsum4(float4& a) {
    a.x = wredsum(a.x); a.y = wredsum(a.y); a.z = wredsum(a.z); a.w = wredsum(a.w);
}
// 8 fp16 weights (one uint4) against 8 beam-float4 activations
__device__ __forceinline__ void fma8(float4& acc, uint4 wv, const float4* o) {
    __half2 h;
    h = *(__half2*)&wv.x; fma4(acc, __low2float(h), o[0]); fma4(acc, __high2float(h), o[1]);
    h = *(__half2*)&wv.y; fma4(acc, __low2float(h), o[2]); fma4(acc, __high2float(h), o[3]);
    h = *(__half2*)&wv.z; fma4(acc, __low2float(h), o[4]); fma4(acc, __high2float(h), o[5]);
    h = *(__half2*)&wv.w; fma4(acc, __low2float(h), o[6]); fma4(acc, __high2float(h), o[7]);
}
__device__ __forceinline__ void fma8s(float& acc, uint4 wv, const float* h) {
    __half2 x;
    x = *(__half2*)&wv.x; acc = fmaf(__low2float(x), h[0], acc); acc = fmaf(__high2float(x), h[1], acc);
    x = *(__half2*)&wv.y; acc = fmaf(__low2float(x), h[2], acc); acc = fmaf(__high2float(x), h[3], acc);
    x = *(__half2*)&wv.z; acc = fmaf(__low2float(x), h[4], acc); acc = fmaf(__high2float(x), h[5], acc);
    x = *(__half2*)&wv.w; acc = fmaf(__low2float(x), h[6], acc); acc = fmaf(__high2float(x), h[7], acc);
}

// top-k comparator: larger value wins; tie -> smaller flat index (JAX top_k)
__device__ __forceinline__ bool cgt(float v1, int i1, float v2, int i2) {
    return (v1 > v2) || (v1 == v2 && i1 < i2);
}
__device__ __forceinline__ void ins4(float* lv, int* li, float v, int idx) {
    if (!cgt(v, idx, lv[3], li[3])) return;
    lv[3] = v; li[3] = idx;
#pragma unroll
    for (int j = 3; j > 0; j--) {
        if (cgt(lv[j], li[j], lv[j - 1], li[j - 1])) {
            float tv = lv[j]; lv[j] = lv[j - 1]; lv[j - 1] = tv;
            int ti = li[j]; li[j] = li[j - 1]; li[j - 1] = ti;
        } else break;
    }
}

// ----------------- fp32 -> fp16 conversion helpers --------------------------
__device__ __forceinline__ uint4 cvt8h(float4 v0, float4 v1) {
    __half2 a = __floats2half2_rn(v0.x, v0.y);
    __half2 b = __floats2half2_rn(v0.z, v0.w);
    __half2 c = __floats2half2_rn(v1.x, v1.y);
    __half2 d = __floats2half2_rn(v1.z, v1.w);
    return make_uint4(*(unsigned*)&a, *(unsigned*)&b, *(unsigned*)&c, *(unsigned*)&d);
}
__device__ __forceinline__ void cvt_range(const float4* __restrict__ src, __half* dst,
                                          size_t n8, size_t start, size_t stride) {
    for (size_t i = start; i < n8; i += stride) {
        float4 a = __ldcs(&src[2 * i]);
        float4 b = __ldcs(&src[2 * i + 1]);
        __stcs(&((uint4*)dst)[i], cvt8h(a, b));
    }
}

// standalone cvt for enc_Whh_f (must precede the fused encoder kernel)
__global__ void k_cvt_enc(const float4* __restrict__ src, int n8) {
    unsigned s = gridDim.x * blockDim.x;
    unsigned i0 = blockIdx.x * blockDim.x + threadIdx.x;
    for (unsigned i = i0; i < (unsigned)n8; i += s) {
        float4 a = __ldcs(&src[2 * (size_t)i]);
        float4 b = __ldcs(&src[2 * (size_t)i + 1]);
        ((uint4*)g_Whhf_h)[i] = cvt8h(a, b);
    }
}

// ----------------- init: zero encoder state -----------------
__global__ void k_init0() {
    int u = threadIdx.x;
    if (u < HH) { g_eh[0][u] = 0.0f; g_eh[1][u] = 0.0f; g_ec[u] = 0.0f; }
}

// ----------------- gather embedded sentence -----------------
__global__ void k_gather(const int* __restrict__ sent, const float* __restrict__ emb) {
    int t = blockIdx.x;
    const float4* src = (const float4*)(emb + (size_t)sent[t] * EE);
    float4* dst = (float4*)(g_X + t * EE);
    for (int e = threadIdx.x; e < EE / 4; e += blockDim.x) dst[e] = src[e];
}

// ----------------- Zx_f = X @ Wih_f^T + b (W row cached in registers) --------
__global__ void k_zxf(const float* __restrict__ W, const float* __restrict__ b) {
    __shared__ __align__(16) float xs[8 * EE];
    int w = threadIdx.x >> 5, lane = threadIdx.x & 31;
    int j = blockIdx.x * 8 + w;
    const float4* wr4 = (const float4*)(W + (size_t)j * EE);
    float4 wreg[8];
#pragma unroll
    for (int i = 0; i < 8; i++) wreg[i] = wr4[lane + 32 * i];
    float bj = b[j];
    for (int tc = 0; tc < 8; tc++) {
        __syncthreads();
        {
            const float4* src = (const float4*)(g_X + tc * 8 * EE);
            float4* dst = (float4*)xs;
            for (int i = threadIdx.x; i < 8 * EE / 4; i += blockDim.x) dst[i] = src[i];
        }
        __syncthreads();
        for (int tt = 0; tt < 8; tt++) {
            float acc = 0.0f;
            const float4* x4 = (const float4*)(xs + tt * EE);
#pragma unroll
            for (int i = 0; i < 8; i++) {
                float4 wv = wreg[i], xv = x4[lane + 32 * i];
                acc = fmaf(wv.x, xv.x, acc); acc = fmaf(wv.y, xv.y, acc);
                acc = fmaf(wv.z, xv.z, acc); acc = fmaf(wv.w, xv.w, acc);
            }
            acc = wredsum(acc);
            if (lane == 0) g_Zf[(tc * 8 + tt) * (4 * HH) + j] = acc + bj;
        }
    }
}

// ----------------- Zb = x_last @ Wih_b^T + b_b (fp32, one-time) -----------------
__global__ void k_zb(const float* __restrict__ W, const float* __restrict__ b) {
    __shared__ __align__(16) float xs[EE];
    {
        const float4* src = (const float4*)(g_X + (SS - 1) * EE);
        float4* dst = (float4*)xs;
        for (int i = threadIdx.x; i < EE / 4; i += blockDim.x) dst[i] = src[i];
    }
    __syncthreads();
    int j = blockIdx.x * 8 + (threadIdx.x >> 5), lane = threadIdx.x & 31;
    const float4* wr4 = (const float4*)(W + (size_t)j * EE);
    const float4* x4 = (const float4*)xs;
    float acc = 0.0f;
#pragma unroll
    for (int i = 0; i < 8; i++) {
        int cq = lane + 32 * i;
        float4 wv = wr4[cq], xv = x4[cq];
        acc = fmaf(wv.x, xv.x, acc); acc = fmaf(wv.y, xv.y, acc);
        acc = fmaf(wv.z, xv.z, acc); acc = fmaf(wv.w, xv.w, acc);
    }
    acc = wredsum(acc);
    if (lane == 0) g_Zb[j] = acc + b[j];
}

// ===== fused: encoder (blocks 0..31) + fp16 conversion (blocks 32..263) =====
__global__ void __launch_bounds__(512, 2)
k_enc_cvt(const float4* __restrict__ Wout32, const float4* __restrict__ Wih32,
          const float4* __restrict__ Whh32, const float4* __restrict__ Wcat32) {
    if (blockIdx.x >= ENCB) {
        size_t start = (size_t)(blockIdx.x - ENCB) * blockDim.x + threadIdx.x;
        size_t stride = (size_t)CVTB * blockDim.x;
        cvt_range(Wout32, g_Wout_h, N8_OUT, start, stride);
        cvt_range(Wih32,  g_Wih_h,  N8_IH,  start, stride);
        cvt_range(Whh32,  g_Whh_h,  N8_HH,  start, stride);
        cvt_range(Wcat32, g_Wcat_h, N8_CAT, start, stride);
        return;
    }
    __shared__ float hT[8 * 64];
    int tid = threadIdx.x;
    int u = blockIdx.x * 16 + (tid >> 5), lane = tid & 31;
    const uint4* WE = (const uint4*)g_Whhf_h;
    for (int t = 0; t < SS; t++) {
        int p = t & 1;
        if (tid < HH)
            hT[(tid & 7) * 64 + (tid >> 3)] = __ldcg(&g_eh[p][tid]);
        __syncthreads();
        float z[4] = {0.f, 0.f, 0.f, 0.f};
#pragma unroll
        for (int i = 0; i < 2; i++) {
            int cq = lane + 32 * i;
            float h[8];
#pragma unroll
            for (int j = 0; j < 8; j++) h[j] = hT[j * 64 + cq];
#pragma unroll
            for (int g = 0; g < 4; g++) {
                uint4 wv = WE[(size_t)(g * HH + u) * 64 + cq];
                fma8s(z[g], wv, h);
            }
        }
#pragma unroll
        for (int g = 0; g < 4; g++) z[g] = wredsum(z[g]);
        if (lane == 0) {
            const float* zx = g_Zf + t * (4 * HH);
            float zi = zx[u] + z[0], zf = zx[HH + u] + z[1];
            float zg = zx[2 * HH + u] + z[2], zo = zx[3 * HH + u] + z[3];
            float c = sigm(zf) * g_ec[u] + sigm(zi) * tanhf(zg);
            g_ec[u] = c;
            g_eh[p ^ 1][u] = sigm(zo) * tanhf(c);
        }
        gridbar(ENCB);
    }
}

// ----------------- backward cell (1 step, h=c=0) + decoder init -----------------
__global__ void k_init2() {
    int u = threadIdx.x;
    if (u < HH) {
        float zi = g_Zb[u], zg = g_Zb[2 * HH + u], zo = g_Zb[3 * HH + u];
        float c = sigm(zi) * tanhf(zg);
        float hb = sigm(zo) * tanhf(c);
        g_sent[u] = g_eh[0][u];
        g_sent[HH + u] = hb;
    }
    __syncthreads();
    for (int d = u; d < DD; d += blockDim.x) {
        float s = g_sent[d];
        g_dh[0][d] = make_float4(s, s, s, s);
        g_dc[0][d] = make_float4(0.f, 0.f, 0.f, 0.f);
    }
    if (u < KKB) {
        g_probs[u] = (u == 0) ? 1.0f : 0.0f;
        g_last[u] = BOSTOK;
        g_fin[u] = 0;
        for (int i = 0; i < TOKL; i++) g_tok[0][u * TOKL + i] = BOSTOK;
    }
    if (u == 0) g_rowctr = NPB;    // prime logits work-steal counter for step 0
}

// ----------------- fused decoder LSTM gates + cat (128 blocks, 1 grid barrier) --
__global__ void k_dec(const float* __restrict__ demb, const float* __restrict__ b,
                      const float* __restrict__ cat_b, int p) {
    __shared__ __align__(16) float4 smA[2048];
    int tid = threadIdx.x;
    int l0 = g_last[0], l1 = g_last[1], l2 = g_last[2], l3 = g_last[3];
    float4* eT = smA;
    float4* hT = smA + 1024;
    for (int a = tid; a < DD; a += blockDim.x) {
        int j = a & 7, cq = a >> 3;
        eT[j * 128 + cq] = make_float4(demb[(size_t)l0 * EE + a], demb[(size_t)l1 * EE + a],
                                       demb[(size_t)l2 * EE + a], demb[(size_t)l3 * EE + a]);
        hT[j * 128 + cq] = g_dh[p][a];
    }
    __syncthreads();
    int u = blockIdx.x * 8 + (tid >> 5), lane = tid & 31;
    const uint4* W1 = (const uint4*)g_Wih_h;
    const uint4* W2 = (const uint4*)g_Whh_h;
    float4 acc[4];
#pragma unroll
    for (int g = 0; g < 4; g++) acc[g] = make_float4(0.f, 0.f, 0.f, 0.f);
#pragma unroll
    for (int i = 0; i < 4; i++) {
        int cq = lane + 32 * i;
        float4 e[8];
#pragma unroll
        for (int j = 0; j < 8; j++) e[j] = eT[j * 128 + cq];
#pragma unroll
        for (int g = 0; g < 4; g++)
            fma8(acc[g], W1[(size_t)(g * DD + u) * 128 + cq], e);
    }
#pragma unroll
    for (int i = 0; i < 4; i++) {
        int cq = lane + 32 * i;
        float4 h[8];
#pragma unroll
        for (int j = 0; j < 8; j++) h[j] = hT[j * 128 + cq];
#pragma unroll
        for (int g = 0; g < 4; g++)
            fma8(acc[g], W2[(size_t)(g * DD + u) * 128 + cq], h);
    }
#pragma unroll
    for (int g = 0; g < 4; g++) redsum4(acc[g]);
    if (lane == 0) {
        float bi = b[u], bf = b[DD + u], bg = b[2 * DD + u], bo = b[3 * DD + u];
        float4 c4 = g_dc[p][u];
        float4 cn, hn;
        cn.x = sigm(acc[1].x + bf) * c4.x + sigm(acc[0].x + bi) * tanhf(acc[2].x + bg);
        cn.y = sigm(acc[1].y + bf) * c4.y + sigm(acc[0].y + bi) * tanhf(acc[2].y + bg);
        cn.z = sigm(acc[1].z + bf) * c4.z + sigm(acc[0].z + bi) * tanhf(acc[2].z + bg);
        cn.w = sigm(acc[1].w + bf) * c4.w + sigm(acc[0].w + bi) * tanhf(acc[2].w + bg);
        hn.x = sigm(acc[3].x + bo) * tanhf(cn.x);
        hn.y = sigm(acc[3].y + bo) * tanhf(cn.y);
        hn.z = sigm(acc[3].z + bo) * tanhf(cn.z);
        hn.w = sigm(acc[3].w + bo) * tanhf(cn.w);
        g_htmp[u] = hn;
        g_ctmp[u] = cn;
    }

    gridbar(128);

    // phase B: outs = tanh([h, emb] @ cat_W^T + cat_b)
    for (int a = tid; a < 2 * DD; a += blockDim.x) {
        int j = a & 7, cq = a >> 3;
        float4 v;
        if (a < DD) v = __ldcg(&g_htmp[a]);
        else {
            int e = a - DD;
            v = make_float4(demb[(size_t)l0 * EE + e], demb[(size_t)l1 * EE + e],
                            demb[(size_t)l2 * EE + e], demb[(size_t)l3 * EE + e]);
        }
        smA[j * 256 + cq] = v;
    }
    __syncthreads();
    const uint4* WC = (const uint4*)g_Wcat_h;
    float4 a4 = make_float4(0.f, 0.f, 0.f, 0.f);
#pragma unroll
    for (int i = 0; i < 8; i++) {
        int cq = lane + 32 * i;
        float4 f[8];
#pragma unroll
        for (int j = 0; j < 8; j++) f[j] = smA[j * 256 + cq];
        fma8(a4, WC[(size_t)u * 256 + cq], f);
    }
    redsum4(a4);
    if (lane == 0) {
        float bd = cat_b[u];
        g_outs[u] = make_float4(tanhf(a4.x + bd), tanhf(a4.y + bd),
                                tanhf(a4.z + bd), tanhf(a4.w + bd));
    }
}

// ----------------- logits: persistent 444 blocks + atomic work-stealing -------
// Each 32-row group computed with identical arithmetic to the fixed-grid
// version -> logits bit-identical. Global max is assignment-invariant.
__global__ void __launch_bounds__(256, 3)
k_logits(const float* __restrict__ b) {
    __shared__ __align__(16) float4 oT[DD];
    __shared__ float4 wmax[8];
    __shared__ unsigned sgrp;
    for (int a = threadIdx.x; a < DD; a += blockDim.x) {
        int j = a & 7, cq = a >> 3;
        oT[j * 128 + cq] = g_outs[a];
    }
    __syncthreads();
    int w = threadIdx.x >> 5, lane = threadIdx.x & 31;
    const uint4* W4 = (const uint4*)g_Wout_h;
    float4 m = make_float4(-INFINITY, -INFINITY, -INFINITY, -INFINITY);
    unsigned grp = blockIdx.x;
    while (grp < NGRP) {
        int vbase = (int)grp * 32 + w * 4;
        float4 acc[4];
#pragma unroll
        for (int r = 0; r < 4; r++) acc[r] = make_float4(0.f, 0.f, 0.f, 0.f);
#pragma unroll
        for (int i = 0; i < 4; i++) {
            int cq = lane + 32 * i;
            float4 o[8];
#pragma unroll
            for (int j = 0; j < 8; j++) o[j] = oT[j * 128 + cq];
#pragma unroll
            for (int r = 0; r < 4; r++) {
                int v = vbase + r; if (v >= VV) v = VV - 1;
                uint4 wv = __ldcs(&W4[(size_t)v * 128 + cq]);
                fma8(acc[r], wv, o);
            }
        }
#pragma unroll
        for (int r = 0; r < 4; r++) {
            redsum4(acc[r]);
            int v = vbase + r;
            if (lane == 0 && v < VV) {
                float bb = b[v];
                acc[r].x += bb; acc[r].y += bb; acc[r].z += bb; acc[r].w += bb;
                g_logits4[v] = acc[r];
                m = max4(m, acc[r]);
            }
        }
        if (threadIdx.x == 0) sgrp = atomicAdd(&g_rowctr, 1u);
        __syncthreads();
        grp = sgrp;
        __syncthreads();
    }
    if (lane == 0) wmax[w] = m;
    __syncthreads();
    if (threadIdx.x == 0) {
        float4 mm = wmax[0];
#pragma unroll
        for (int i = 1; i < 8; i++) mm = max4(mm, wmax[i]);
        g_bmax4[blockIdx.x] = mm;
    }
}

// ----------------- fused select: expsum + topk + final (64 blocks, 2 barriers) --
__global__ void k_select(int t, int p, float* out, int out_size) {
    __shared__ float4 red[256];
    __shared__ float cv[256][4];
    __shared__ int   ci[256][4];
    __shared__ int parent[4], tokn[4], nfin[4];
    __shared__ float topv[4];
    int tid = threadIdx.x, blk = blockIdx.x;

    float4 m = make_float4(-INFINITY, -INFINITY, -INFINITY, -INFINITY);
    for (int i = tid; i < NPB; i += 256) m = max4(m, g_bmax4[i]);
    red[tid] = m; __syncthreads();
    for (int s = 128; s; s >>= 1) {
        if (tid < s) red[tid] = max4(red[tid], red[tid + s]);
        __syncthreads();
    }
    float4 gm = red[0]; __syncthreads();

    float4 sum = make_float4(0.f, 0.f, 0.f, 0.f);
    int base = blk * VCH;
    for (int i = tid; i < VCH; i += 256) {
        int v = base + i;
        if (v >= VV) break;
        float4 l = g_logits4[v];
        sum.x += expf(l.x - gm.x); sum.y += expf(l.y - gm.y);
        sum.z += expf(l.z - gm.z); sum.w += expf(l.w - gm.w);
    }
    red[tid] = sum; __syncthreads();
    for (int s = 128; s; s >>= 1) {
        if (tid < s) red[tid] = add4(red[tid], red[tid + s]);
        __syncthreads();
    }
    if (tid == 0) g_bsum4[blk] = red[0];

    gridbar(NSB);

    float4 sm = (tid < NSB) ? __ldcg(&g_bsum4[tid]) : make_float4(0.f, 0.f, 0.f, 0.f);
    red[tid] = sm; __syncthreads();
    for (int s = 128; s; s >>= 1) {
        if (tid < s) red[tid] = add4(red[tid], red[tid + s]);
        __syncthreads();
    }
    float4 tot = red[0]; __syncthreads();

    float pr[4] = {g_probs[0], g_probs[1], g_probs[2], g_probs[3]};
    int   fn[4] = {g_fin[0], g_fin[1], g_fin[2], g_fin[3]};
    float gmk[4] = {gm.x, gm.y, gm.z, gm.w};
    float tk[4]  = {tot.x, tot.y, tot.z, tot.w};

    float lv[4] = {-INFINITY, -INFINITY, -INFINITY, -INFINITY};
    int   li[4] = {INT_MAX, INT_MAX, INT_MAX, INT_MAX};
    for (int i = tid; i < VCH; i += 256) {
        int v = base + i;
        if (v >= VV) break;
        float4 l = g_logits4[v];
        float lk[4] = {l.x, l.y, l.z, l.w};
#pragma unroll
        for (int k = 0; k < 4; k++) {
            float pp = fn[k] ? (v == EOSTOK ? 1.0f : 0.0f)
                             : fdiv_rn(expf(lk[k] - gmk[k]), tk[k]);
            ins4(lv, li, pmul_ftz(pr[k], pp), k * VV + v);  // FTZ: DO NOT CHANGE
        }
    }
#pragma unroll
    for (int k = 0; k < 4; k++) { cv[tid][k] = lv[k]; ci[tid][k] = li[k]; }
    __syncthreads();
    for (int s = 128; s; s >>= 1) {
        if (tid < s) {
            float av[4]; int ai[4];
#pragma unroll
            for (int k = 0; k < 4; k++) { av[k] = cv[tid][k]; ai[k] = ci[tid][k]; }
#pragma unroll
            for (int k = 0; k < 4; k++) ins4(av, ai, cv[tid + s][k], ci[tid + s][k]);
#pragma unroll
            for (int k = 0; k < 4; k++) { cv[tid][k] = av[k]; ci[tid][k] = ai[k]; }
        }
        __syncthreads();
    }
    if (tid == 0) {
#pragma unroll
        for (int k = 0; k < 4; k++) { g_tval[blk * 4 + k] = cv[0][k]; g_tidx[blk * 4 + k] = ci[0][k]; }
    }

    gridbar(NSB);

    if (blk != 0) return;

    if (tid < NSB) {
#pragma unroll
        for (int k = 0; k < 4; k++) {
            cv[tid][k] = __ldcg(&g_tval[tid * 4 + k]);
            ci[tid][k] = __ldcg(&g_tidx[tid * 4 + k]);
        }
    }
    __syncthreads();
    for (int s = 32; s; s >>= 1) {
        if (tid < s) {
            float av[4]; int ai[4];
#pragma unroll
            for (int k = 0; k < 4; k++) { av[k] = cv[tid][k]; ai[k] = ci[tid][k]; }
#pragma unroll
            for (int k = 0; k < 4; k++) ins4(av, ai, cv[tid + s][k], ci[tid + s][k]);
#pragma unroll
            for (int k = 0; k < 4; k++) { cv[tid][k] = av[k]; ci[tid][k] = ai[k]; }
        }
        __syncthreads();
    }
    if (tid == 0) {
        int ofin[4] = {g_fin[0], g_fin[1], g_fin[2], g_fin[3]};
#pragma unroll
        for (int k = 0; k < 4; k++) {
            topv[k] = cv[0][k];
            int idx = ci[0][k];
            parent[k] = idx / VV;
            tokn[k] = idx % VV;
            nfin[k] = ofin[idx / VV] | ((idx % VV) == EOSTOK);
        }
        g_rowctr = NPB;   // re-prime logits work-steal counter for next step
    }
    __syncthreads();

    if (tid < KKB * TOKL) {
        int k = tid / TOKL, i = tid % TOKL;
        int val = (i == t + 1) ? tokn[k] : g_tok[p][parent[k] * TOKL + i];
        g_tok[p ^ 1][k * TOKL + i] = val;
    }
    for (int d = tid; d < DD; d += blockDim.x) {
        float4 h = g_htmp[d], c = g_ctmp[d];
        float hh[4] = {h.x, h.y, h.z, h.w};
        float cc[4] = {c.x, c.y, c.z, c.w};
        g_dh[p ^ 1][d] = make_float4(hh[parent[0]], hh[parent[1]], hh[parent[2]], hh[parent[3]]);
        g_dc[p ^ 1][d] = make_float4(cc[parent[0]], cc[parent[1]], cc[parent[2]], cc[parent[3]]);
    }
    if (tid < KKB) {
        g_probs[tid] = topv[tid];
        g_last[tid] = tokn[tid];
        g_fin[tid] = nfin[tid];
    }
    __syncthreads();

    if (t == MAXLEN - 1 && tid == 0) {
        int best = 0; float bv = topv[0];
        for (int k = 1; k < 4; k++) if (topv[k] > bv) { bv = topv[k]; best = k; }
        if (out_size >= TOKL + KKB) {
            for (int i = 0; i < TOKL; i++) out[i] = (float)g_tok[p ^ 1][best * TOKL + i];
            for (int k = 0; k < KKB; k++) out[TOKL + k] = topv[k];
        } else if (out_size == TOKL) {
            int* io = (int*)out;
            for (int i = 0; i < TOKL; i++) io[i] = g_tok[p ^ 1][best * TOKL + i];
        } else if (out_size == KKB) {
            for (int k = 0; k < KKB; k++) out[k] = topv[k];
        } else {
            int n = out_size < TOKL ? out_size : TOKL;
            for (int i = 0; i < n; i++) out[i] = (float)g_tok[p ^ 1][best * TOKL + i];
        }
    }
}

// ----------------- launch -----------------
extern "C" void kernel_launch(void* const* d_in, const int* in_sizes, int n_in,
                              void* d_out, int out_size) {
    const int*   sent      = (const int*)d_in[0];
    const float* enc_emb   = (const float*)d_in[1];
    const float* enc_Wih_f = (const float*)d_in[2];
    const float* enc_Whh_f = (const float*)d_in[3];
    const float* enc_b_f   = (const float*)d_in[4];
    const float* enc_Wih_b = (const float*)d_in[5];
    /* enc_Whh_b (d_in[6]) unused: backward LSTM only runs 1 step with h=0 */
    const float* enc_b_b   = (const float*)d_in[7];
    const float* dec_emb   = (const float*)d_in[8];
    const float* dec_Wih   = (const float*)d_in[9];
    const float* dec_Whh   = (const float*)d_in[10];
    const float* dec_b     = (const float*)d_in[11];
    const float* cat_W     = (const float*)d_in[12];
    const float* cat_b     = (const float*)d_in[13];
    const float* out_W     = (const float*)d_in[14];
    const float* out_b     = (const float*)d_in[15];
    (void)in_sizes; (void)n_in;

    k_init0<<<1, 512>>>();
    k_gather<<<SS, 256>>>(sent, enc_emb);
    {
        int n8 = (4 * HH * HH) / 8;
        k_cvt_enc<<<148, 512>>>((const float4*)enc_Whh_f, n8);
    }
    k_zxf<<<256, 256>>>(enc_Wih_f, enc_b_f);
    k_zb<<<256, 256>>>(enc_Wih_b, enc_b_b);
    k_enc_cvt<<<ENCB + CVTB, 512>>>((const float4*)out_W, (const float4*)dec_Wih,
                                    (const float4*)dec_Whh, (const float4*)cat_W);
    k_init2<<<1, 512>>>();

    for (int t = 0; t < MAXLEN; t++) {
        int p = t & 1;
        k_dec<<<128, 256>>>(dec_emb, dec_b, cat_b, p);
        k_logits<<<NPB, 256>>>(out_b);
        k_select<<<NSB, 256>>>(t, p, (float*)d_out, out_size);
    }
}